// round 1
// baseline (speedup 1.0000x reference)
#include <cuda_runtime.h>
#include <cuda_bf16.h>
#include <math.h>

// Problem constants
constexpr int B = 2, S = 2048, H = 16, D = 64, E = 1024; // E = H*D = ATT_DIM
constexpr int M_TOT = B * S;                              // 4096

// Scratch (device globals — allocation-free)
__device__ float g_Q[(size_t)B * H * S * D];
__device__ float g_K[(size_t)B * H * S * D];
__device__ float g_V[(size_t)B * H * S * D];
__device__ float g_Y[(size_t)M_TOT * E];

// log2(10000)
__device__ __forceinline__ float rope_sin(int s, int j) {
    // theta_j = 10000^(-j/16) = 2^(-j * log2(10000)/16)
    float theta = exp2f(-(float)j * (13.287712379549449f / 16.0f));
    return sinf((float)s * theta);
}

// ---------------------------------------------------------------------------
// QKV projection GEMM + fused RoPE epilogue.
// C[4096,1024] = X[4096,1024] @ W[1024,1024]; tile 64x64, BK=16, 256 thr, 4x4.
// blockIdx.z: 0=Q, 1=K (RoPE), 2=V (no RoPE). Output layout [B,H,S,D].
// ---------------------------------------------------------------------------
__global__ __launch_bounds__(256) void qkv_kernel(
    const float* __restrict__ x,
    const float* __restrict__ Wq,
    const float* __restrict__ Wk,
    const float* __restrict__ Wv)
{
    __shared__ float As[16][64];
    __shared__ float Bs[16][64];
    __shared__ float Cs[64][68];

    const int which = blockIdx.z;
    const float* __restrict__ W = (which == 0) ? Wq : (which == 1) ? Wk : Wv;
    float* out = (which == 0) ? g_Q : (which == 1) ? g_K : g_V;

    const int tid = threadIdx.x;
    const int tx = tid & 15, ty = tid >> 4;
    const int row0 = blockIdx.y * 64;
    const int col0 = blockIdx.x * 64;

    float acc[4][4] = {};

    for (int k0 = 0; k0 < E; k0 += 16) {
        // Load X tile [64 rows x 16 k] transposed into As[k][r]
        {
            int r  = tid >> 2;
            int kq = (tid & 3) * 4;
            float4 v = *reinterpret_cast<const float4*>(&x[(row0 + r) * E + k0 + kq]);
            As[kq + 0][r] = v.x; As[kq + 1][r] = v.y;
            As[kq + 2][r] = v.z; As[kq + 3][r] = v.w;
        }
        // Load W tile [16 k x 64 n]
        #pragma unroll
        for (int it = 0; it < 4; it++) {
            int idx = tid + it * 256;
            int kk = idx >> 6, c = idx & 63;
            Bs[kk][c] = W[(k0 + kk) * E + col0 + c];
        }
        __syncthreads();

        #pragma unroll
        for (int kk = 0; kk < 16; kk++) {
            float4 a4 = *reinterpret_cast<const float4*>(&As[kk][ty * 4]);
            float4 b4 = *reinterpret_cast<const float4*>(&Bs[kk][tx * 4]);
            float av[4] = {a4.x, a4.y, a4.z, a4.w};
            float bv[4] = {b4.x, b4.y, b4.z, b4.w};
            #pragma unroll
            for (int i = 0; i < 4; i++)
                #pragma unroll
                for (int j = 0; j < 4; j++)
                    acc[i][j] = fmaf(av[i], bv[j], acc[i][j]);
        }
        __syncthreads();
    }

    // Stage tile for RoPE pairing (partner is d ^ 32, tile-local since tile N == head dim)
    #pragma unroll
    for (int i = 0; i < 4; i++)
        #pragma unroll
        for (int j = 0; j < 4; j++)
            Cs[ty * 4 + i][tx * 4 + j] = acc[i][j];
    __syncthreads();

    const bool rope = (which < 2);
    const int h = col0 >> 6;
    #pragma unroll
    for (int it = 0; it < 16; it++) {
        int e = tid + it * 256;
        int r = e >> 6, d = e & 63;
        int grow = row0 + r;
        int b = grow >> 11;       // / 2048
        int s = grow & 2047;
        float val;
        if (rope) {
            // Reference uses sin for BOTH terms (c = sin):
            // d<32 : sin * (v[d] - v[d+32]);  d>=32 : sin * (v[d] + v[d-32])
            int j = d & 31;
            float sn = rope_sin(s, j);
            float v0 = Cs[r][d];
            float vp = Cs[r][d ^ 32];
            val = (d < 32) ? sn * (v0 - vp) : sn * (v0 + vp);
        } else {
            val = Cs[r][d];
        }
        out[(((b * H + h) * S) + s) * D + d] = val;
    }
}

// ---------------------------------------------------------------------------
// Flash attention, fp32, causal. One CTA per (q-tile 64, head, batch).
// Online softmax; 1/8 scale folded into Q at load. Writes Y as [B, S, H*D].
// ---------------------------------------------------------------------------
constexpr int ATTN_SMEM = 4 * 64 * 68 * 4; // Qt, Kt, Vs, Pt : 69632 B

__global__ __launch_bounds__(256, 2) void attn_kernel()
{
    extern __shared__ float sm[];
    float (*Qt)[68] = (float(*)[68])(sm);               // [d][i]
    float (*Kt)[68] = (float(*)[68])(sm + 1 * 64 * 68); // [d][j]
    float (*Vs)[68] = (float(*)[68])(sm + 2 * 64 * 68); // [j][d]
    float (*Pt)[68] = (float(*)[68])(sm + 3 * 64 * 68); // [j][i]

    const int qt = blockIdx.x, h = blockIdx.y, b = blockIdx.z;
    const int tid = threadIdx.x;
    const int tx = tid & 15, ty = tid >> 4;
    const int base = ((b * H + h) * S) * D;
    const int q0 = qt * 64;

    // Load Q tile transposed, pre-scaled by softmax scale 1/8
    #pragma unroll
    for (int it = 0; it < 16; it++) {
        int e = tid + it * 256;
        int i = e >> 6, d = e & 63;
        Qt[d][i] = g_Q[base + (q0 + i) * D + d] * 0.125f;
    }

    float m[4], l[4], o[4][4];
    #pragma unroll
    for (int i = 0; i < 4; i++) {
        m[i] = -1e30f; l[i] = 0.0f;
        #pragma unroll
        for (int j = 0; j < 4; j++) o[i][j] = 0.0f;
    }

    for (int kt = 0; kt <= qt; kt++) {
        __syncthreads(); // prev iter's smem reads done; also covers Qt load at kt==0
        const int k0 = kt * 64;
        #pragma unroll
        for (int it = 0; it < 16; it++) {
            int e = tid + it * 256;
            int j = e >> 6, d = e & 63;
            Kt[d][j] = g_K[base + (k0 + j) * D + d];
            Vs[j][d] = g_V[base + (k0 + j) * D + d];
        }
        __syncthreads();

        // Scores: sc[i][j] = sum_d Qt[d][i] * Kt[d][j]
        float sc[4][4] = {};
        #pragma unroll 16
        for (int d = 0; d < 64; d++) {
            float4 q4 = *reinterpret_cast<const float4*>(&Qt[d][ty * 4]);
            float4 k4 = *reinterpret_cast<const float4*>(&Kt[d][tx * 4]);
            float qa[4] = {q4.x, q4.y, q4.z, q4.w};
            float ka[4] = {k4.x, k4.y, k4.z, k4.w};
            #pragma unroll
            for (int i = 0; i < 4; i++)
                #pragma unroll
                for (int j = 0; j < 4; j++)
                    sc[i][j] = fmaf(qa[i], ka[j], sc[i][j]);
        }

        // Causal mask on the diagonal tile
        if (kt == qt) {
            #pragma unroll
            for (int i = 0; i < 4; i++)
                #pragma unroll
                for (int j = 0; j < 4; j++)
                    if (k0 + tx * 4 + j > q0 + ty * 4 + i) sc[i][j] = -1e30f;
        }

        // Online softmax update (row stats replicated across the 16 tx lanes)
        #pragma unroll
        for (int i = 0; i < 4; i++) {
            float mx = fmaxf(fmaxf(sc[i][0], sc[i][1]), fmaxf(sc[i][2], sc[i][3]));
            mx = fmaxf(mx, __shfl_xor_sync(0xFFFFFFFFu, mx, 1));
            mx = fmaxf(mx, __shfl_xor_sync(0xFFFFFFFFu, mx, 2));
            mx = fmaxf(mx, __shfl_xor_sync(0xFFFFFFFFu, mx, 4));
            mx = fmaxf(mx, __shfl_xor_sync(0xFFFFFFFFu, mx, 8));
            float mnew = fmaxf(m[i], mx);
            float corr = __expf(m[i] - mnew);
            float rs = 0.0f;
            #pragma unroll
            for (int j = 0; j < 4; j++) {
                float p = __expf(sc[i][j] - mnew);
                sc[i][j] = p;
                rs += p;
            }
            rs += __shfl_xor_sync(0xFFFFFFFFu, rs, 1);
            rs += __shfl_xor_sync(0xFFFFFFFFu, rs, 2);
            rs += __shfl_xor_sync(0xFFFFFFFFu, rs, 4);
            rs += __shfl_xor_sync(0xFFFFFFFFu, rs, 8);
            l[i] = l[i] * corr + rs;
            m[i] = mnew;
            #pragma unroll
            for (int j = 0; j < 4; j++) o[i][j] *= corr;
        }

        // Stage P transposed
        #pragma unroll
        for (int i = 0; i < 4; i++)
            #pragma unroll
            for (int j = 0; j < 4; j++)
                Pt[tx * 4 + j][ty * 4 + i] = sc[i][j];
        __syncthreads();

        // O += P @ V
        #pragma unroll 16
        for (int j = 0; j < 64; j++) {
            float4 p4 = *reinterpret_cast<const float4*>(&Pt[j][ty * 4]);
            float4 v4 = *reinterpret_cast<const float4*>(&Vs[j][tx * 4]);
            float pa[4] = {p4.x, p4.y, p4.z, p4.w};
            float va[4] = {v4.x, v4.y, v4.z, v4.w};
            #pragma unroll
            for (int i = 0; i < 4; i++)
                #pragma unroll
                for (int dd = 0; dd < 4; dd++)
                    o[i][dd] = fmaf(pa[i], va[dd], o[i][dd]);
        }
    }

    // Normalize and write Y in [B, S, H*D]
    #pragma unroll
    for (int i = 0; i < 4; i++) {
        float inv = 1.0f / l[i];
        int srow = q0 + ty * 4 + i;
        float4 st;
        st.x = o[i][0] * inv; st.y = o[i][1] * inv;
        st.z = o[i][2] * inv; st.w = o[i][3] * inv;
        *reinterpret_cast<float4*>(&g_Y[(b * S + srow) * E + h * 64 + tx * 4]) = st;
    }
}

// ---------------------------------------------------------------------------
// Output projection: out = Y @ Wo + bo
// ---------------------------------------------------------------------------
__global__ __launch_bounds__(256) void out_proj_kernel(
    const float* __restrict__ Wo,
    const float* __restrict__ bo,
    float* __restrict__ out)
{
    __shared__ float As[16][64];
    __shared__ float Bs[16][64];

    const int tid = threadIdx.x;
    const int tx = tid & 15, ty = tid >> 4;
    const int row0 = blockIdx.y * 64;
    const int col0 = blockIdx.x * 64;

    float acc[4][4] = {};

    for (int k0 = 0; k0 < E; k0 += 16) {
        {
            int r  = tid >> 2;
            int kq = (tid & 3) * 4;
            float4 v = *reinterpret_cast<const float4*>(&g_Y[(row0 + r) * E + k0 + kq]);
            As[kq + 0][r] = v.x; As[kq + 1][r] = v.y;
            As[kq + 2][r] = v.z; As[kq + 3][r] = v.w;
        }
        #pragma unroll
        for (int it = 0; it < 4; it++) {
            int idx = tid + it * 256;
            int kk = idx >> 6, c = idx & 63;
            Bs[kk][c] = Wo[(k0 + kk) * E + col0 + c];
        }
        __syncthreads();

        #pragma unroll
        for (int kk = 0; kk < 16; kk++) {
            float4 a4 = *reinterpret_cast<const float4*>(&As[kk][ty * 4]);
            float4 b4 = *reinterpret_cast<const float4*>(&Bs[kk][tx * 4]);
            float av[4] = {a4.x, a4.y, a4.z, a4.w};
            float bv[4] = {b4.x, b4.y, b4.z, b4.w};
            #pragma unroll
            for (int i = 0; i < 4; i++)
                #pragma unroll
                for (int j = 0; j < 4; j++)
                    acc[i][j] = fmaf(av[i], bv[j], acc[i][j]);
        }
        __syncthreads();
    }

    float4 bv4 = *reinterpret_cast<const float4*>(&bo[col0 + tx * 4]);
    #pragma unroll
    for (int i = 0; i < 4; i++) {
        float4 st;
        st.x = acc[i][0] + bv4.x;
        st.y = acc[i][1] + bv4.y;
        st.z = acc[i][2] + bv4.z;
        st.w = acc[i][3] + bv4.w;
        *reinterpret_cast<float4*>(&out[(row0 + ty * 4 + i) * E + col0 + tx * 4]) = st;
    }
}

// ---------------------------------------------------------------------------
extern "C" void kernel_launch(void* const* d_in, const int* in_sizes, int n_in,
                              void* d_out, int out_size)
{
    (void)in_sizes; (void)n_in; (void)out_size;
    const float* x  = (const float*)d_in[0];
    const float* Wq = (const float*)d_in[1];
    const float* Wk = (const float*)d_in[2];
    const float* Wv = (const float*)d_in[3];
    const float* Wo = (const float*)d_in[4];
    const float* bo = (const float*)d_in[5];
    float* out = (float*)d_out;

    cudaFuncSetAttribute(attn_kernel,
                         cudaFuncAttributeMaxDynamicSharedMemorySize, ATTN_SMEM);

    dim3 g1(E / 64, M_TOT / 64, 3);
    qkv_kernel<<<g1, 256>>>(x, Wq, Wk, Wv);

    dim3 g2(S / 64, H, B);
    attn_kernel<<<g2, 256, ATTN_SMEM>>>();

    dim3 g3(E / 64, M_TOT / 64);
    out_proj_kernel<<<g3, 256>>>(Wo, bo, out);
}

// round 3
// speedup vs baseline: 1.7164x; 1.7164x over previous
#include <cuda_runtime.h>
#include <cuda_bf16.h>
#include <cstdint>
#include <math.h>

// Problem constants
constexpr int B = 2, S = 2048, H = 16, D = 64, E = 1024; // E = H*D
constexpr int M_TOT = B * S;                              // 4096

// Scratch (device globals — allocation-free)
__device__ float g_Q[(size_t)B * H * S * D];
__device__ float g_K[(size_t)B * H * S * D];
__device__ float g_V[(size_t)B * H * S * D];
__device__ float g_Y[(size_t)M_TOT * E];
__device__ float g_sin[(size_t)S * 32];

// ---------------------------------------------------------------------------
// RoPE sin table: sin(s * theta_j), theta_j = 10000^(-j/16), j in [0,32)
// (reference uses sin for BOTH rope terms: c = sin bug replicated)
// ---------------------------------------------------------------------------
__global__ void sin_kernel() {
    int i = blockIdx.x * 256 + threadIdx.x;
    if (i < S * 32) {
        int s = i >> 5, j = i & 31;
        float theta = exp2f(-(float)j * (13.287712379549449f / 16.0f));
        g_sin[i] = sinf((float)s * theta);
    }
}

// ---------------------------------------------------------------------------
// tf32 helpers
// ---------------------------------------------------------------------------
__device__ __forceinline__ uint32_t f2tf(float f) {
    uint32_t u;
    asm("cvt.rna.tf32.f32 %0, %1;" : "=r"(u) : "f"(f));
    return u;
}

__device__ __forceinline__ void mma_tf32(float c[4],
                                         uint32_t a0, uint32_t a1, uint32_t a2, uint32_t a3,
                                         uint32_t b0, uint32_t b1) {
    asm volatile(
        "mma.sync.aligned.m16n8k8.row.col.f32.tf32.tf32.f32 "
        "{%0,%1,%2,%3},{%4,%5,%6,%7},{%8,%9},{%0,%1,%2,%3};"
        : "+f"(c[0]), "+f"(c[1]), "+f"(c[2]), "+f"(c[3])
        : "r"(a0), "r"(a1), "r"(a2), "r"(a3), "r"(b0), "r"(b1));
}

// ---------------------------------------------------------------------------
// Shared tf32 GEMM mainloop: C[128,128] tile of  Ag[4096,1024] @ Bg[1024,1024]
// smem: As[2][16][136] (k-major, XOR-swizzled m), Bs[2][16][136] (k-major).
// 8 warps (2m x 4n), warp tile 64x32, m16n8k8.
// ---------------------------------------------------------------------------
constexpr int LDT = 136;                 // smem pitch (words)
constexpr int STAGE_W = 16 * LDT;        // words per stage per operand
constexpr int GEMM_SMEM_W = 4 * STAGE_W; // As[2] + Bs[2]

struct LdgRegs {
    float4 xr0, xr1, wr0, wr1;
};

struct GemmCtx {
    const float* Ag;
    const float* Bg;
    int row0, col0;
    int xm0, xm1, xq;     // A-load coords
    int wk0, wk1, wnq;    // B-load coords
    int wm, wn, gid, tig; // mma coords
};

__device__ __forceinline__ void ldg_stage(const GemmCtx& g, int k0, LdgRegs& r) {
    r.xr0 = *(const float4*)&g.Ag[(size_t)(g.row0 + g.xm0) * E + k0 + g.xq];
    r.xr1 = *(const float4*)&g.Ag[(size_t)(g.row0 + g.xm1) * E + k0 + g.xq];
    r.wr0 = *(const float4*)&g.Bg[(size_t)(k0 + g.wk0) * E + g.col0 + g.wnq];
    r.wr1 = *(const float4*)&g.Bg[(size_t)(k0 + g.wk1) * E + g.col0 + g.wnq];
}

__device__ __forceinline__ void sts_stage(const GemmCtx& g, const LdgRegs& r,
                                          uint32_t* a, uint32_t* b) {
    float xv0[4] = {r.xr0.x, r.xr0.y, r.xr0.z, r.xr0.w};
    float xv1[4] = {r.xr1.x, r.xr1.y, r.xr1.z, r.xr1.w};
    #pragma unroll
    for (int i = 0; i < 4; i++) {
        int k = g.xq + i;
        int shf = (k & 12) << 1;
        a[k * LDT + (g.xm0 ^ shf)] = f2tf(xv0[i]);
        a[k * LDT + (g.xm1 ^ shf)] = f2tf(xv1[i]);
    }
    uint4 p0 = make_uint4(f2tf(r.wr0.x), f2tf(r.wr0.y), f2tf(r.wr0.z), f2tf(r.wr0.w));
    uint4 p1 = make_uint4(f2tf(r.wr1.x), f2tf(r.wr1.y), f2tf(r.wr1.z), f2tf(r.wr1.w));
    *(uint4*)&b[g.wk0 * LDT + g.wnq] = p0;
    *(uint4*)&b[g.wk1 * LDT + g.wnq] = p1;
}

__device__ __forceinline__ void mma_stage(const GemmCtx& g, const uint32_t* a,
                                          const uint32_t* b, float (&acc)[4][4][4]) {
    #pragma unroll
    for (int kk = 0; kk < 2; kk++) {
        int k0 = kk * 8;
        int r0 = k0 + g.tig, r1 = k0 + g.tig + 4;
        int s0 = (r0 & 12) << 1, s1 = (r1 & 12) << 1;
        uint32_t af[4][4], bf[4][2];
        #pragma unroll
        for (int im = 0; im < 4; im++) {
            int mb = g.wm * 64 + im * 16 + g.gid;
            af[im][0] = a[r0 * LDT + ((mb)     ^ s0)];
            af[im][1] = a[r0 * LDT + ((mb + 8) ^ s0)];
            af[im][2] = a[r1 * LDT + ((mb)     ^ s1)];
            af[im][3] = a[r1 * LDT + ((mb + 8) ^ s1)];
        }
        #pragma unroll
        for (int in = 0; in < 4; in++) {
            int nb = g.wn * 32 + in * 8 + g.gid;
            bf[in][0] = b[r0 * LDT + nb];
            bf[in][1] = b[r1 * LDT + nb];
        }
        #pragma unroll
        for (int im = 0; im < 4; im++)
            #pragma unroll
            for (int in = 0; in < 4; in++)
                mma_tf32(acc[im][in], af[im][0], af[im][1], af[im][2], af[im][3],
                         bf[in][0], bf[in][1]);
    }
}

__device__ __forceinline__ void gemm128(const float* __restrict__ Ag,
                                        const float* __restrict__ Bg,
                                        int row0, int col0,
                                        uint32_t* sm, float (&acc)[4][4][4], int tid)
{
    uint32_t* As = sm;
    uint32_t* Bs = sm + 2 * STAGE_W;

    GemmCtx g;
    g.Ag = Ag; g.Bg = Bg; g.row0 = row0; g.col0 = col0;
    const int lane = tid & 31;
    const int warp = tid >> 5;
    g.wm = warp >> 2;
    g.wn = warp & 3;
    g.gid = lane >> 2;
    g.tig = lane & 3;
    g.xm0 = tid >> 2;  g.xm1 = (tid + 256) >> 2;
    g.xq  = (tid & 3) * 4;
    g.wk0 = tid >> 5;  g.wk1 = (tid + 256) >> 5;
    g.wnq = (tid & 31) * 4;

    LdgRegs r;
    ldg_stage(g, 0, r);
    sts_stage(g, r, As, Bs);

    const int NS = E / 16; // 64 stages
    for (int s = 0; s < NS; s++) {
        __syncthreads();
        if (s + 1 < NS) ldg_stage(g, (s + 1) * 16, r);
        int cur = s & 1, nxt = (s + 1) & 1;
        mma_stage(g, As + cur * STAGE_W, Bs + cur * STAGE_W, acc);
        if (s + 1 < NS) sts_stage(g, r, As + nxt * STAGE_W, Bs + nxt * STAGE_W);
    }
}

// ---------------------------------------------------------------------------
// QKV projection (tf32 mma) + fused RoPE epilogue. Output layout [B,H,S,D].
// blockIdx.z: 0=Q, 1=K (RoPE), 2=V. Tile 128 rows x 128 cols (= 2 heads).
// ---------------------------------------------------------------------------
constexpr int QKV_SMEM = 128 * 132 * 4; // 67584 B (>= GEMM_SMEM_W*4 = 34816)

__global__ __launch_bounds__(256) void qkv_kernel(
    const float* __restrict__ x,
    const float* __restrict__ Wq,
    const float* __restrict__ Wk,
    const float* __restrict__ Wv)
{
    extern __shared__ uint32_t sm[];
    const int which = blockIdx.z;
    const float* __restrict__ W = (which == 0) ? Wq : (which == 1) ? Wk : Wv;
    float* out = (which == 0) ? g_Q : (which == 1) ? g_K : g_V;

    const int tid = threadIdx.x;
    const int row0 = blockIdx.y * 128;
    const int col0 = blockIdx.x * 128;

    float acc[4][4][4] = {};
    gemm128(x, W, row0, col0, sm, acc, tid);
    __syncthreads();

    // Stage C to smem for RoPE pairing (d ^ 32 is tile-local)
    float* Cs = (float*)sm; // [128][132]
    {
        const int lane = tid & 31, warp = tid >> 5;
        const int wm = warp >> 2, wn = warp & 3;
        const int gid = lane >> 2, tig = lane & 3;
        #pragma unroll
        for (int im = 0; im < 4; im++)
            #pragma unroll
            for (int in = 0; in < 4; in++) {
                int r = wm * 64 + im * 16 + gid;
                int c = wn * 32 + in * 8 + 2 * tig;
                Cs[r * 132 + c]           = acc[im][in][0];
                Cs[r * 132 + c + 1]       = acc[im][in][1];
                Cs[(r + 8) * 132 + c]     = acc[im][in][2];
                Cs[(r + 8) * 132 + c + 1] = acc[im][in][3];
            }
    }
    __syncthreads();

    const bool rope = (which < 2);
    const int h0 = col0 >> 6;
    #pragma unroll 4
    for (int it = 0; it < 64; it++) {
        int e = tid + it * 256;
        int r = e >> 7, c = e & 127;
        int grow = row0 + r;
        int b = grow >> 11, s = grow & 2047;
        int h = h0 + (c >> 6), d = c & 63;
        float val;
        if (rope) {
            float sn = g_sin[(s << 5) + (d & 31)];
            float v0 = Cs[r * 132 + c];
            float vp = Cs[r * 132 + (c ^ 32)];
            val = (d < 32) ? sn * (v0 - vp) : sn * (v0 + vp);
        } else {
            val = Cs[r * 132 + c];
        }
        out[(((b * H + h) * S) + s) * D + d] = val;
    }
}

// ---------------------------------------------------------------------------
// Output projection: out = Y @ Wo + bo (tf32 mma, direct epilogue)
// ---------------------------------------------------------------------------
__global__ __launch_bounds__(256) void out_proj_kernel(
    const float* __restrict__ Wo,
    const float* __restrict__ bo,
    float* __restrict__ out)
{
    extern __shared__ uint32_t sm[];
    const int tid = threadIdx.x;
    const int row0 = blockIdx.y * 128;
    const int col0 = blockIdx.x * 128;

    float acc[4][4][4] = {};
    gemm128(g_Y, Wo, row0, col0, sm, acc, tid);

    const int lane = tid & 31, warp = tid >> 5;
    const int wm = warp >> 2, wn = warp & 3;
    const int gid = lane >> 2, tig = lane & 3;

    #pragma unroll
    for (int im = 0; im < 4; im++)
        #pragma unroll
        for (int in = 0; in < 4; in++) {
            int r = row0 + wm * 64 + im * 16 + gid;
            int c = col0 + wn * 32 + in * 8 + 2 * tig;
            float b0 = bo[c], b1 = bo[c + 1];
            float2 v0 = make_float2(acc[im][in][0] + b0, acc[im][in][1] + b1);
            float2 v1 = make_float2(acc[im][in][2] + b0, acc[im][in][3] + b1);
            *(float2*)&out[(size_t)r * E + c]       = v0;
            *(float2*)&out[(size_t)(r + 8) * E + c] = v1;
        }
}

// ---------------------------------------------------------------------------
// Flash attention, fp32, causal (unchanged from R1).
// ---------------------------------------------------------------------------
constexpr int ATTN_SMEM = 4 * 64 * 68 * 4; // 69632 B

__global__ __launch_bounds__(256, 2) void attn_kernel()
{
    extern __shared__ float smf[];
    float (*Qt)[68] = (float(*)[68])(smf);
    float (*Kt)[68] = (float(*)[68])(smf + 1 * 64 * 68);
    float (*Vs)[68] = (float(*)[68])(smf + 2 * 64 * 68);
    float (*Pt)[68] = (float(*)[68])(smf + 3 * 64 * 68);

    const int qt = blockIdx.x, h = blockIdx.y, b = blockIdx.z;
    const int tid = threadIdx.x;
    const int tx = tid & 15, ty = tid >> 4;
    const int base = ((b * H + h) * S) * D;
    const int q0 = qt * 64;

    #pragma unroll
    for (int it = 0; it < 16; it++) {
        int e = tid + it * 256;
        int i = e >> 6, d = e & 63;
        Qt[d][i] = g_Q[base + (q0 + i) * D + d] * 0.125f;
    }

    float m[4], l[4], o[4][4];
    #pragma unroll
    for (int i = 0; i < 4; i++) {
        m[i] = -1e30f; l[i] = 0.0f;
        #pragma unroll
        for (int j = 0; j < 4; j++) o[i][j] = 0.0f;
    }

    for (int kt = 0; kt <= qt; kt++) {
        __syncthreads();
        const int k0 = kt * 64;
        #pragma unroll
        for (int it = 0; it < 16; it++) {
            int e = tid + it * 256;
            int j = e >> 6, d = e & 63;
            Kt[d][j] = g_K[base + (k0 + j) * D + d];
            Vs[j][d] = g_V[base + (k0 + j) * D + d];
        }
        __syncthreads();

        float sc[4][4] = {};
        #pragma unroll 16
        for (int d = 0; d < 64; d++) {
            float4 q4 = *reinterpret_cast<const float4*>(&Qt[d][ty * 4]);
            float4 k4 = *reinterpret_cast<const float4*>(&Kt[d][tx * 4]);
            float qa[4] = {q4.x, q4.y, q4.z, q4.w};
            float ka[4] = {k4.x, k4.y, k4.z, k4.w};
            #pragma unroll
            for (int i = 0; i < 4; i++)
                #pragma unroll
                for (int j = 0; j < 4; j++)
                    sc[i][j] = fmaf(qa[i], ka[j], sc[i][j]);
        }

        if (kt == qt) {
            #pragma unroll
            for (int i = 0; i < 4; i++)
                #pragma unroll
                for (int j = 0; j < 4; j++)
                    if (k0 + tx * 4 + j > q0 + ty * 4 + i) sc[i][j] = -1e30f;
        }

        #pragma unroll
        for (int i = 0; i < 4; i++) {
            float mx = fmaxf(fmaxf(sc[i][0], sc[i][1]), fmaxf(sc[i][2], sc[i][3]));
            mx = fmaxf(mx, __shfl_xor_sync(0xFFFFFFFFu, mx, 1));
            mx = fmaxf(mx, __shfl_xor_sync(0xFFFFFFFFu, mx, 2));
            mx = fmaxf(mx, __shfl_xor_sync(0xFFFFFFFFu, mx, 4));
            mx = fmaxf(mx, __shfl_xor_sync(0xFFFFFFFFu, mx, 8));
            float mnew = fmaxf(m[i], mx);
            float corr = __expf(m[i] - mnew);
            float rs = 0.0f;
            #pragma unroll
            for (int j = 0; j < 4; j++) {
                float p = __expf(sc[i][j] - mnew);
                sc[i][j] = p;
                rs += p;
            }
            rs += __shfl_xor_sync(0xFFFFFFFFu, rs, 1);
            rs += __shfl_xor_sync(0xFFFFFFFFu, rs, 2);
            rs += __shfl_xor_sync(0xFFFFFFFFu, rs, 4);
            rs += __shfl_xor_sync(0xFFFFFFFFu, rs, 8);
            l[i] = l[i] * corr + rs;
            m[i] = mnew;
            #pragma unroll
            for (int j = 0; j < 4; j++) o[i][j] *= corr;
        }

        #pragma unroll
        for (int i = 0; i < 4; i++)
            #pragma unroll
            for (int j = 0; j < 4; j++)
                Pt[tx * 4 + j][ty * 4 + i] = sc[i][j];
        __syncthreads();

        #pragma unroll 16
        for (int j = 0; j < 64; j++) {
            float4 p4 = *reinterpret_cast<const float4*>(&Pt[j][ty * 4]);
            float4 v4 = *reinterpret_cast<const float4*>(&Vs[j][tx * 4]);
            float pa[4] = {p4.x, p4.y, p4.z, p4.w};
            float va[4] = {v4.x, v4.y, v4.z, v4.w};
            #pragma unroll
            for (int i = 0; i < 4; i++)
                #pragma unroll
                for (int dd = 0; dd < 4; dd++)
                    o[i][dd] = fmaf(pa[i], va[dd], o[i][dd]);
        }
    }

    #pragma unroll
    for (int i = 0; i < 4; i++) {
        float inv = 1.0f / l[i];
        int srow = q0 + ty * 4 + i;
        float4 st;
        st.x = o[i][0] * inv; st.y = o[i][1] * inv;
        st.z = o[i][2] * inv; st.w = o[i][3] * inv;
        *reinterpret_cast<float4*>(&g_Y[(b * S + srow) * E + h * 64 + tx * 4]) = st;
    }
}

// ---------------------------------------------------------------------------
extern "C" void kernel_launch(void* const* d_in, const int* in_sizes, int n_in,
                              void* d_out, int out_size)
{
    (void)in_sizes; (void)n_in; (void)out_size;
    const float* x  = (const float*)d_in[0];
    const float* Wq = (const float*)d_in[1];
    const float* Wk = (const float*)d_in[2];
    const float* Wv = (const float*)d_in[3];
    const float* Wo = (const float*)d_in[4];
    const float* bo = (const float*)d_in[5];
    float* out = (float*)d_out;

    cudaFuncSetAttribute(qkv_kernel,
                         cudaFuncAttributeMaxDynamicSharedMemorySize, QKV_SMEM);
    cudaFuncSetAttribute(attn_kernel,
                         cudaFuncAttributeMaxDynamicSharedMemorySize, ATTN_SMEM);

    sin_kernel<<<(S * 32 + 255) / 256, 256>>>();

    dim3 g1(E / 128, M_TOT / 128, 3);
    qkv_kernel<<<g1, 256, QKV_SMEM>>>(x, Wq, Wk, Wv);

    dim3 g2(S / 64, H, B);
    attn_kernel<<<g2, 256, ATTN_SMEM>>>();

    dim3 g3(E / 128, M_TOT / 128);
    out_proj_kernel<<<g3, 256, GEMM_SMEM_W * 4>>>(Wo, bo, out);
}

// round 4
// speedup vs baseline: 2.8911x; 1.6844x over previous
#include <cuda_runtime.h>
#include <cuda_bf16.h>
#include <cstdint>
#include <math.h>

// Problem constants
constexpr int B = 2, S = 2048, H = 16, D = 64, E = 1024; // E = H*D
constexpr int M_TOT = B * S;                              // 4096

// Scratch (device globals — allocation-free)
__device__ float g_Q[(size_t)B * H * S * D];
__device__ float g_K[(size_t)B * H * S * D];
__device__ float g_V[(size_t)B * H * S * D];
__device__ float g_Y[(size_t)M_TOT * E];
__device__ float g_sin[(size_t)S * 32];

// ---------------------------------------------------------------------------
// RoPE sin table (reference's c = sin bug replicated)
// ---------------------------------------------------------------------------
__global__ void sin_kernel() {
    int i = blockIdx.x * 256 + threadIdx.x;
    if (i < S * 32) {
        int s = i >> 5, j = i & 31;
        float theta = exp2f(-(float)j * (13.287712379549449f / 16.0f));
        g_sin[i] = sinf((float)s * theta);
    }
}

// ---------------------------------------------------------------------------
// tf32 helpers
// ---------------------------------------------------------------------------
__device__ __forceinline__ uint32_t f2tf(float f) {
    uint32_t u;
    asm("cvt.rna.tf32.f32 %0, %1;" : "=r"(u) : "f"(f));
    return u;
}

__device__ __forceinline__ void mma_tf32(float c[4],
                                         uint32_t a0, uint32_t a1, uint32_t a2, uint32_t a3,
                                         uint32_t b0, uint32_t b1) {
    asm volatile(
        "mma.sync.aligned.m16n8k8.row.col.f32.tf32.tf32.f32 "
        "{%0,%1,%2,%3},{%4,%5,%6,%7},{%8,%9},{%0,%1,%2,%3};"
        : "+f"(c[0]), "+f"(c[1]), "+f"(c[2]), "+f"(c[3])
        : "r"(a0), "r"(a1), "r"(a2), "r"(a3), "r"(b0), "r"(b1));
}

// ---------------------------------------------------------------------------
// Shared tf32 GEMM mainloop (unchanged from R3)
// ---------------------------------------------------------------------------
constexpr int LDT = 136;
constexpr int STAGE_W = 16 * LDT;
constexpr int GEMM_SMEM_W = 4 * STAGE_W;

struct LdgRegs { float4 xr0, xr1, wr0, wr1; };

struct GemmCtx {
    const float* Ag;
    const float* Bg;
    int row0, col0;
    int xm0, xm1, xq;
    int wk0, wk1, wnq;
    int wm, wn, gid, tig;
};

__device__ __forceinline__ void ldg_stage(const GemmCtx& g, int k0, LdgRegs& r) {
    r.xr0 = *(const float4*)&g.Ag[(size_t)(g.row0 + g.xm0) * E + k0 + g.xq];
    r.xr1 = *(const float4*)&g.Ag[(size_t)(g.row0 + g.xm1) * E + k0 + g.xq];
    r.wr0 = *(const float4*)&g.Bg[(size_t)(k0 + g.wk0) * E + g.col0 + g.wnq];
    r.wr1 = *(const float4*)&g.Bg[(size_t)(k0 + g.wk1) * E + g.col0 + g.wnq];
}

__device__ __forceinline__ void sts_stage(const GemmCtx& g, const LdgRegs& r,
                                          uint32_t* a, uint32_t* b) {
    float xv0[4] = {r.xr0.x, r.xr0.y, r.xr0.z, r.xr0.w};
    float xv1[4] = {r.xr1.x, r.xr1.y, r.xr1.z, r.xr1.w};
    #pragma unroll
    for (int i = 0; i < 4; i++) {
        int k = g.xq + i;
        int shf = (k & 12) << 1;
        a[k * LDT + (g.xm0 ^ shf)] = f2tf(xv0[i]);
        a[k * LDT + (g.xm1 ^ shf)] = f2tf(xv1[i]);
    }
    uint4 p0 = make_uint4(f2tf(r.wr0.x), f2tf(r.wr0.y), f2tf(r.wr0.z), f2tf(r.wr0.w));
    uint4 p1 = make_uint4(f2tf(r.wr1.x), f2tf(r.wr1.y), f2tf(r.wr1.z), f2tf(r.wr1.w));
    *(uint4*)&b[g.wk0 * LDT + g.wnq] = p0;
    *(uint4*)&b[g.wk1 * LDT + g.wnq] = p1;
}

__device__ __forceinline__ void mma_stage(const GemmCtx& g, const uint32_t* a,
                                          const uint32_t* b, float (&acc)[4][4][4]) {
    #pragma unroll
    for (int kk = 0; kk < 2; kk++) {
        int k0 = kk * 8;
        int r0 = k0 + g.tig, r1 = k0 + g.tig + 4;
        int s0 = (r0 & 12) << 1, s1 = (r1 & 12) << 1;
        uint32_t af[4][4], bf[4][2];
        #pragma unroll
        for (int im = 0; im < 4; im++) {
            int mb = g.wm * 64 + im * 16 + g.gid;
            af[im][0] = a[r0 * LDT + ((mb)     ^ s0)];
            af[im][1] = a[r0 * LDT + ((mb + 8) ^ s0)];
            af[im][2] = a[r1 * LDT + ((mb)     ^ s1)];
            af[im][3] = a[r1 * LDT + ((mb + 8) ^ s1)];
        }
        #pragma unroll
        for (int in = 0; in < 4; in++) {
            int nb = g.wn * 32 + in * 8 + g.gid;
            bf[in][0] = b[r0 * LDT + nb];
            bf[in][1] = b[r1 * LDT + nb];
        }
        #pragma unroll
        for (int im = 0; im < 4; im++)
            #pragma unroll
            for (int in = 0; in < 4; in++)
                mma_tf32(acc[im][in], af[im][0], af[im][1], af[im][2], af[im][3],
                         bf[in][0], bf[in][1]);
    }
}

__device__ __forceinline__ void gemm128(const float* __restrict__ Ag,
                                        const float* __restrict__ Bg,
                                        int row0, int col0,
                                        uint32_t* sm, float (&acc)[4][4][4], int tid)
{
    uint32_t* As = sm;
    uint32_t* Bs = sm + 2 * STAGE_W;

    GemmCtx g;
    g.Ag = Ag; g.Bg = Bg; g.row0 = row0; g.col0 = col0;
    const int lane = tid & 31;
    const int warp = tid >> 5;
    g.wm = warp >> 2;
    g.wn = warp & 3;
    g.gid = lane >> 2;
    g.tig = lane & 3;
    g.xm0 = tid >> 2;  g.xm1 = (tid + 256) >> 2;
    g.xq  = (tid & 3) * 4;
    g.wk0 = tid >> 5;  g.wk1 = (tid + 256) >> 5;
    g.wnq = (tid & 31) * 4;

    LdgRegs r;
    ldg_stage(g, 0, r);
    sts_stage(g, r, As, Bs);

    const int NS = E / 16;
    for (int s = 0; s < NS; s++) {
        __syncthreads();
        if (s + 1 < NS) ldg_stage(g, (s + 1) * 16, r);
        int cur = s & 1, nxt = (s + 1) & 1;
        mma_stage(g, As + cur * STAGE_W, Bs + cur * STAGE_W, acc);
        if (s + 1 < NS) sts_stage(g, r, As + nxt * STAGE_W, Bs + nxt * STAGE_W);
    }
}

// ---------------------------------------------------------------------------
// QKV projection + fused RoPE epilogue (unchanged from R3)
// ---------------------------------------------------------------------------
constexpr int QKV_SMEM = 128 * 132 * 4;

__global__ __launch_bounds__(256) void qkv_kernel(
    const float* __restrict__ x,
    const float* __restrict__ Wq,
    const float* __restrict__ Wk,
    const float* __restrict__ Wv)
{
    extern __shared__ uint32_t sm[];
    const int which = blockIdx.z;
    const float* __restrict__ W = (which == 0) ? Wq : (which == 1) ? Wk : Wv;
    float* out = (which == 0) ? g_Q : (which == 1) ? g_K : g_V;

    const int tid = threadIdx.x;
    const int row0 = blockIdx.y * 128;
    const int col0 = blockIdx.x * 128;

    float acc[4][4][4] = {};
    gemm128(x, W, row0, col0, sm, acc, tid);
    __syncthreads();

    float* Cs = (float*)sm; // [128][132]
    {
        const int lane = tid & 31, warp = tid >> 5;
        const int wm = warp >> 2, wn = warp & 3;
        const int gid = lane >> 2, tig = lane & 3;
        #pragma unroll
        for (int im = 0; im < 4; im++)
            #pragma unroll
            for (int in = 0; in < 4; in++) {
                int r = wm * 64 + im * 16 + gid;
                int c = wn * 32 + in * 8 + 2 * tig;
                Cs[r * 132 + c]           = acc[im][in][0];
                Cs[r * 132 + c + 1]       = acc[im][in][1];
                Cs[(r + 8) * 132 + c]     = acc[im][in][2];
                Cs[(r + 8) * 132 + c + 1] = acc[im][in][3];
            }
    }
    __syncthreads();

    const bool rope = (which < 2);
    const int h0 = col0 >> 6;
    #pragma unroll 4
    for (int it = 0; it < 64; it++) {
        int e = tid + it * 256;
        int r = e >> 7, c = e & 127;
        int grow = row0 + r;
        int b = grow >> 11, s = grow & 2047;
        int h = h0 + (c >> 6), d = c & 63;
        float val;
        if (rope) {
            float sn = g_sin[(s << 5) + (d & 31)];
            float v0 = Cs[r * 132 + c];
            float vp = Cs[r * 132 + (c ^ 32)];
            val = (d < 32) ? sn * (v0 - vp) : sn * (v0 + vp);
        } else {
            val = Cs[r * 132 + c];
        }
        out[(((b * H + h) * S) + s) * D + d] = val;
    }
}

// ---------------------------------------------------------------------------
// Output projection (unchanged from R3)
// ---------------------------------------------------------------------------
__global__ __launch_bounds__(256) void out_proj_kernel(
    const float* __restrict__ Wo,
    const float* __restrict__ bo,
    float* __restrict__ out)
{
    extern __shared__ uint32_t sm[];
    const int tid = threadIdx.x;
    const int row0 = blockIdx.y * 128;
    const int col0 = blockIdx.x * 128;

    float acc[4][4][4] = {};
    gemm128(g_Y, Wo, row0, col0, sm, acc, tid);

    const int lane = tid & 31, warp = tid >> 5;
    const int wm = warp >> 2, wn = warp & 3;
    const int gid = lane >> 2, tig = lane & 3;

    #pragma unroll
    for (int im = 0; im < 4; im++)
        #pragma unroll
        for (int in = 0; in < 4; in++) {
            int r = row0 + wm * 64 + im * 16 + gid;
            int c = col0 + wn * 32 + in * 8 + 2 * tig;
            float b0 = bo[c], b1 = bo[c + 1];
            float2 v0 = make_float2(acc[im][in][0] + b0, acc[im][in][1] + b1);
            float2 v1 = make_float2(acc[im][in][2] + b0, acc[im][in][3] + b1);
            *(float2*)&out[(size_t)r * E + c]       = v0;
            *(float2*)&out[(size_t)(r + 8) * E + c] = v1;
        }
}

// ---------------------------------------------------------------------------
// Flash attention with tf32 tensor cores.
// CTA = 128 queries x (b,h). 8 warps, each owns 16 rows. K-tile = 64 keys.
// smem (tf32 bits): Qs[128][68], Ks[64][68], Vt[64][68] (d-major), Ps[128][68].
// ---------------------------------------------------------------------------
constexpr int AP = 68; // smem pitch (words)
constexpr int ATTN_SMEM = (128 * AP + 64 * AP + 64 * AP + 128 * AP) * 4; // 104448 B

__global__ __launch_bounds__(256, 1) void attn_kernel()
{
    extern __shared__ uint32_t sm[];
    uint32_t* Qs = sm;                    // [128][AP]
    uint32_t* Ks = Qs + 128 * AP;         // [64][AP]  (j-major: row j holds d)
    uint32_t* Vt = Ks + 64 * AP;          // [64][AP]  (d-major: row d holds j)
    uint32_t* Ps = Vt + 64 * AP;          // [128][AP]

    const int qt = (gridDim.x - 1) - blockIdx.x; // heavy tiles first
    const int h = blockIdx.y, b = blockIdx.z;
    const int tid = threadIdx.x;
    const int w = tid >> 5, lane = tid & 31;
    const int gid = lane >> 2, tig = lane & 3;
    const int base = ((b * H + h) * S) * D;
    const int q0 = qt * 128;

    // Load Q (scaled by 1/8, converted to tf32)
    #pragma unroll
    for (int it = 0; it < 32; it++) {
        int idx = tid + it * 256;
        int row = idx >> 6, d = idx & 63;
        Qs[row * AP + d] = f2tf(g_Q[base + (q0 + row) * D + d] * 0.125f);
    }

    const int r0 = w * 16 + gid;  // tile-local row (and r0+8)
    const int grow0 = q0 + r0;

    float m0 = -1e30f, m1 = -1e30f, l0 = 0.0f, l1 = 0.0f;
    float o[8][4] = {};

    const int NKT = 2 * qt + 2;
    for (int kt = 0; kt < NKT; kt++) {
        __syncthreads(); // previous iter's Vt reads done (covers Q load at kt==0)
        const int k0 = kt * 64;
        #pragma unroll
        for (int it = 0; it < 16; it++) {
            int idx = tid + it * 256;
            int j = idx >> 6, d = idx & 63;
            float kv = g_K[base + (k0 + j) * D + d];
            float vv = g_V[base + (k0 + j) * D + d];
            Ks[j * AP + d] = f2tf(kv);
            Vt[d * AP + j] = f2tf(vv);
        }
        __syncthreads();

        // S = Q @ K^T  (warp rows r0..r0+15, cols 0..63)
        float sacc[8][4] = {};
        #pragma unroll
        for (int kk = 0; kk < 8; kk++) {
            int d0 = kk * 8;
            uint32_t a0 = Qs[r0 * AP + d0 + tig];
            uint32_t a1 = Qs[(r0 + 8) * AP + d0 + tig];
            uint32_t a2 = Qs[r0 * AP + d0 + tig + 4];
            uint32_t a3 = Qs[(r0 + 8) * AP + d0 + tig + 4];
            #pragma unroll
            for (int in = 0; in < 8; in++) {
                uint32_t b0 = Ks[(in * 8 + gid) * AP + d0 + tig];
                uint32_t b1 = Ks[(in * 8 + gid) * AP + d0 + tig + 4];
                mma_tf32(sacc[in], a0, a1, a2, a3, b0, b1);
            }
        }

        // Causal mask (only last two k-tiles can cross the diagonal)
        if (kt >= 2 * qt) {
            #pragma unroll
            for (int in = 0; in < 8; in++) {
                int gc = k0 + in * 8 + 2 * tig;
                if (gc     > grow0)     sacc[in][0] = -1e30f;
                if (gc + 1 > grow0)     sacc[in][1] = -1e30f;
                if (gc     > grow0 + 8) sacc[in][2] = -1e30f;
                if (gc + 1 > grow0 + 8) sacc[in][3] = -1e30f;
            }
        }

        // Online softmax (rows r0 and r0+8; reduce over the 4 tig lanes)
        float mx0 = -1e30f, mx1 = -1e30f;
        #pragma unroll
        for (int in = 0; in < 8; in++) {
            mx0 = fmaxf(mx0, fmaxf(sacc[in][0], sacc[in][1]));
            mx1 = fmaxf(mx1, fmaxf(sacc[in][2], sacc[in][3]));
        }
        mx0 = fmaxf(mx0, __shfl_xor_sync(0xFFFFFFFFu, mx0, 1));
        mx0 = fmaxf(mx0, __shfl_xor_sync(0xFFFFFFFFu, mx0, 2));
        mx1 = fmaxf(mx1, __shfl_xor_sync(0xFFFFFFFFu, mx1, 1));
        mx1 = fmaxf(mx1, __shfl_xor_sync(0xFFFFFFFFu, mx1, 2));
        float mn0 = fmaxf(m0, mx0), mn1 = fmaxf(m1, mx1);
        float cr0 = __expf(m0 - mn0), cr1 = __expf(m1 - mn1);

        float rs0 = 0.0f, rs1 = 0.0f;
        #pragma unroll
        for (int in = 0; in < 8; in++) {
            float p0 = __expf(sacc[in][0] - mn0);
            float p1 = __expf(sacc[in][1] - mn0);
            float p2 = __expf(sacc[in][2] - mn1);
            float p3 = __expf(sacc[in][3] - mn1);
            rs0 += p0 + p1;
            rs1 += p2 + p3;
            uint2 w0 = make_uint2(f2tf(p0), f2tf(p1));
            uint2 w1 = make_uint2(f2tf(p2), f2tf(p3));
            *(uint2*)&Ps[r0 * AP + in * 8 + 2 * tig]       = w0;
            *(uint2*)&Ps[(r0 + 8) * AP + in * 8 + 2 * tig] = w1;
        }
        rs0 += __shfl_xor_sync(0xFFFFFFFFu, rs0, 1);
        rs0 += __shfl_xor_sync(0xFFFFFFFFu, rs0, 2);
        rs1 += __shfl_xor_sync(0xFFFFFFFFu, rs1, 1);
        rs1 += __shfl_xor_sync(0xFFFFFFFFu, rs1, 2);
        l0 = l0 * cr0 + rs0;
        l1 = l1 * cr1 + rs1;
        m0 = mn0; m1 = mn1;
        #pragma unroll
        for (int in = 0; in < 8; in++) {
            o[in][0] *= cr0; o[in][1] *= cr0;
            o[in][2] *= cr1; o[in][3] *= cr1;
        }
        __syncwarp(); // warp's own P rows written by warp itself

        // O += P @ V
        #pragma unroll
        for (int kk = 0; kk < 8; kk++) {
            int j0 = kk * 8;
            uint32_t a0 = Ps[r0 * AP + j0 + tig];
            uint32_t a1 = Ps[(r0 + 8) * AP + j0 + tig];
            uint32_t a2 = Ps[r0 * AP + j0 + tig + 4];
            uint32_t a3 = Ps[(r0 + 8) * AP + j0 + tig + 4];
            #pragma unroll
            for (int in = 0; in < 8; in++) {
                uint32_t b0 = Vt[(in * 8 + gid) * AP + j0 + tig];
                uint32_t b1 = Vt[(in * 8 + gid) * AP + j0 + tig + 4];
                mma_tf32(o[in], a0, a1, a2, a3, b0, b1);
            }
        }
    }

    // Epilogue: normalize and write Y in [B, S, H*D]
    float inv0 = 1.0f / l0, inv1 = 1.0f / l1;
    #pragma unroll
    for (int in = 0; in < 8; in++) {
        int c = h * 64 + in * 8 + 2 * tig;
        float2 v0 = make_float2(o[in][0] * inv0, o[in][1] * inv0);
        float2 v1 = make_float2(o[in][2] * inv1, o[in][3] * inv1);
        *(float2*)&g_Y[(size_t)(b * S + grow0) * E + c]     = v0;
        *(float2*)&g_Y[(size_t)(b * S + grow0 + 8) * E + c] = v1;
    }
}

// ---------------------------------------------------------------------------
extern "C" void kernel_launch(void* const* d_in, const int* in_sizes, int n_in,
                              void* d_out, int out_size)
{
    (void)in_sizes; (void)n_in; (void)out_size;
    const float* x  = (const float*)d_in[0];
    const float* Wq = (const float*)d_in[1];
    const float* Wk = (const float*)d_in[2];
    const float* Wv = (const float*)d_in[3];
    const float* Wo = (const float*)d_in[4];
    const float* bo = (const float*)d_in[5];
    float* out = (float*)d_out;

    cudaFuncSetAttribute(qkv_kernel,
                         cudaFuncAttributeMaxDynamicSharedMemorySize, QKV_SMEM);
    cudaFuncSetAttribute(attn_kernel,
                         cudaFuncAttributeMaxDynamicSharedMemorySize, ATTN_SMEM);

    sin_kernel<<<(S * 32 + 255) / 256, 256>>>();

    dim3 g1(E / 128, M_TOT / 128, 3);
    qkv_kernel<<<g1, 256, QKV_SMEM>>>(x, Wq, Wk, Wv);

    dim3 g2(S / 128, H, B);
    attn_kernel<<<g2, 256, ATTN_SMEM>>>();

    dim3 g3(E / 128, M_TOT / 128);
    out_proj_kernel<<<g3, 256, GEMM_SMEM_W * 4>>>(Wo, bo, out);
}

// round 5
// speedup vs baseline: 3.0371x; 1.0505x over previous
#include <cuda_runtime.h>
#include <cuda_bf16.h>
#include <cstdint>
#include <math.h>

// Problem constants
constexpr int B = 2, S = 2048, H = 16, D = 64, E = 1024; // E = H*D
constexpr int M_TOT = B * S;                              // 4096

// Scratch (device globals — allocation-free). All hold tf32 bit patterns.
__device__ uint32_t g_Q[(size_t)B * H * S * D];
__device__ uint32_t g_K[(size_t)B * H * S * D];
__device__ uint32_t g_V[(size_t)B * H * S * D];
__device__ uint32_t g_Y[(size_t)M_TOT * E];
// tf32-converted inputs: [X: 0..4M) [Wq: 4M..5M) [Wk: 5M..6M) [Wv: 6M..7M) [Wo: 7M..8M)
constexpr size_t TF_X  = 0;
constexpr size_t TF_WQ = (size_t)4 * 1024 * 1024;
constexpr size_t TF_WK = (size_t)5 * 1024 * 1024;
constexpr size_t TF_WV = (size_t)6 * 1024 * 1024;
constexpr size_t TF_WO = (size_t)7 * 1024 * 1024;
__device__ uint32_t g_tf[(size_t)8 * 1024 * 1024];
__device__ float g_sin[(size_t)S * 32];

// ---------------------------------------------------------------------------
// tf32 helpers
// ---------------------------------------------------------------------------
__device__ __forceinline__ uint32_t f2tf(float f) {
    uint32_t u;
    asm("cvt.rna.tf32.f32 %0, %1;" : "=r"(u) : "f"(f));
    return u;
}

__device__ __forceinline__ void mma_tf32(float c[4],
                                         uint32_t a0, uint32_t a1, uint32_t a2, uint32_t a3,
                                         uint32_t b0, uint32_t b1) {
    asm volatile(
        "mma.sync.aligned.m16n8k8.row.col.f32.tf32.tf32.f32 "
        "{%0,%1,%2,%3},{%4,%5,%6,%7},{%8,%9},{%0,%1,%2,%3};"
        : "+f"(c[0]), "+f"(c[1]), "+f"(c[2]), "+f"(c[3])
        : "r"(a0), "r"(a1), "r"(a2), "r"(a3), "r"(b0), "r"(b1));
}

__device__ __forceinline__ void cp16(uint32_t dst, const uint32_t* src) {
    asm volatile("cp.async.cg.shared.global [%0], [%1], 16;" :: "r"(dst), "l"(src));
}

// ---------------------------------------------------------------------------
// RoPE sin table (reference's c = sin bug replicated)
// ---------------------------------------------------------------------------
__global__ void sin_kernel() {
    int i = blockIdx.x * 256 + threadIdx.x;
    if (i < S * 32) {
        int s = i >> 5, j = i & 31;
        float theta = exp2f(-(float)j * (13.287712379549449f / 16.0f));
        g_sin[i] = sinf((float)s * theta);
    }
}

// ---------------------------------------------------------------------------
// Convert inputs to tf32 bits (8M elements, float4-vectorized)
// ---------------------------------------------------------------------------
__global__ __launch_bounds__(256) void cvt_kernel(
    const float* __restrict__ x,  const float* __restrict__ Wq,
    const float* __restrict__ Wk, const float* __restrict__ Wv,
    const float* __restrict__ Wo)
{
    size_t i = ((size_t)blockIdx.x * 256 + threadIdx.x) * 4;
    const float* src;
    size_t off;
    if (i < TF_WQ)      { src = x;  off = i; }
    else if (i < TF_WK) { src = Wq; off = i - TF_WQ; }
    else if (i < TF_WV) { src = Wk; off = i - TF_WK; }
    else if (i < TF_WO) { src = Wv; off = i - TF_WV; }
    else                { src = Wo; off = i - TF_WO; }
    float4 v = *(const float4*)&src[off];
    uint4 o = make_uint4(f2tf(v.x), f2tf(v.y), f2tf(v.z), f2tf(v.w));
    *(uint4*)&g_tf[i] = o;
}

// ---------------------------------------------------------------------------
// cp.async 4-stage tf32 GEMM mainloop. C[128,128] = A[4096,1024] @ B[1024,1024]
// A stage: [128][20] row-major (pitch 20 -> conflict-free fragments)
// B stage: [16][136] k-major  (pitch 136 -> conflict-free fragments)
// 8 warps (2m x 4n), warp tile 64x32, m16n8k8.
// ---------------------------------------------------------------------------
constexpr int NSTG = 4;
constexpr int AP_A = 20;
constexpr int AP_B = 136;
constexpr int ASTG_W = 128 * AP_A;       // 2560 words
constexpr int BSTG_W = 16 * AP_B;        // 2176 words
constexpr int STG_W  = ASTG_W + BSTG_W;  // 4736 words
constexpr int GEMM_SMEM = NSTG * STG_W * 4; // 75776 B

__device__ __forceinline__ void gemm_issue(const uint32_t* Ag, const uint32_t* Bg,
                                           int row0, int col0, int k0,
                                           uint32_t abase, uint32_t bbase, int tid)
{
    int r0 = tid >> 2, kq = (tid & 3) * 4;
    cp16(abase + (uint32_t)(r0 * AP_A + kq) * 4,
         Ag + (size_t)(row0 + r0) * E + k0 + kq);
    cp16(abase + (uint32_t)((r0 + 64) * AP_A + kq) * 4,
         Ag + (size_t)(row0 + r0 + 64) * E + k0 + kq);
    int kr = tid >> 5, nq = (tid & 31) * 4;
    cp16(bbase + (uint32_t)(kr * AP_B + nq) * 4,
         Bg + (size_t)(k0 + kr) * E + col0 + nq);
    cp16(bbase + (uint32_t)((kr + 8) * AP_B + nq) * 4,
         Bg + (size_t)(k0 + kr + 8) * E + col0 + nq);
}

__device__ __forceinline__ void gemm_mma(const uint32_t* a, const uint32_t* b,
                                         float (&acc)[4][4][4],
                                         int wm, int wn, int gid, int tig)
{
    #pragma unroll
    for (int kk = 0; kk < 2; kk++) {
        int kc = kk * 8;
        uint32_t af[4][4], bf[4][2];
        #pragma unroll
        for (int im = 0; im < 4; im++) {
            int mb = wm * 64 + im * 16 + gid;
            af[im][0] = a[mb * AP_A + kc + tig];
            af[im][1] = a[(mb + 8) * AP_A + kc + tig];
            af[im][2] = a[mb * AP_A + kc + tig + 4];
            af[im][3] = a[(mb + 8) * AP_A + kc + tig + 4];
        }
        #pragma unroll
        for (int in = 0; in < 4; in++) {
            int nb = wn * 32 + in * 8 + gid;
            bf[in][0] = b[(kc + tig) * AP_B + nb];
            bf[in][1] = b[(kc + tig + 4) * AP_B + nb];
        }
        #pragma unroll
        for (int im = 0; im < 4; im++)
            #pragma unroll
            for (int in = 0; in < 4; in++)
                mma_tf32(acc[im][in], af[im][0], af[im][1], af[im][2], af[im][3],
                         bf[in][0], bf[in][1]);
    }
}

__device__ __forceinline__ void gemm128(const uint32_t* __restrict__ Ag,
                                        const uint32_t* __restrict__ Bg,
                                        int row0, int col0,
                                        uint32_t* sm, float (&acc)[4][4][4], int tid)
{
    const int lane = tid & 31, warp = tid >> 5;
    const int wm = warp >> 2, wn = warp & 3;
    const int gid = lane >> 2, tig = lane & 3;

    uint32_t smbase = (uint32_t)__cvta_generic_to_shared(sm);

    #pragma unroll
    for (int p = 0; p < 3; p++) {
        uint32_t ab = smbase + (uint32_t)(p * STG_W) * 4;
        gemm_issue(Ag, Bg, row0, col0, p * 16, ab, ab + ASTG_W * 4, tid);
        asm volatile("cp.async.commit_group;" ::: "memory");
    }

    const int NS = E / 16; // 64
    for (int s = 0; s < NS; s++) {
        asm volatile("cp.async.wait_group 2;" ::: "memory");
        __syncthreads();
        if (s + 3 < NS) {
            int st = (s + 3) & 3;
            uint32_t ab = smbase + (uint32_t)(st * STG_W) * 4;
            gemm_issue(Ag, Bg, row0, col0, (s + 3) * 16, ab, ab + ASTG_W * 4, tid);
        }
        asm volatile("cp.async.commit_group;" ::: "memory");
        int cur = s & 3;
        gemm_mma(sm + cur * STG_W, sm + cur * STG_W + ASTG_W, acc, wm, wn, gid, tig);
    }
}

// ---------------------------------------------------------------------------
// QKV projection + fused RoPE epilogue. Outputs tf32 bits, layout [B,H,S,D].
// Q additionally pre-scaled by 1/8 (softmax scale).
// ---------------------------------------------------------------------------
constexpr int QKV_SMEM = (GEMM_SMEM > 128 * 132 * 4) ? GEMM_SMEM : 128 * 132 * 4;

__global__ __launch_bounds__(256) void qkv_kernel()
{
    extern __shared__ uint32_t sm[];
    const int which = blockIdx.z;
    const uint32_t* W = g_tf + ((which == 0) ? TF_WQ : (which == 1) ? TF_WK : TF_WV);
    uint32_t* out = (which == 0) ? g_Q : (which == 1) ? g_K : g_V;

    const int tid = threadIdx.x;
    const int row0 = blockIdx.y * 128;
    const int col0 = blockIdx.x * 128;

    float acc[4][4][4] = {};
    gemm128(g_tf + TF_X, W, row0, col0, sm, acc, tid);
    __syncthreads();

    float* Cs = (float*)sm; // [128][132]
    {
        const int lane = tid & 31, warp = tid >> 5;
        const int wm = warp >> 2, wn = warp & 3;
        const int gid = lane >> 2, tig = lane & 3;
        #pragma unroll
        for (int im = 0; im < 4; im++)
            #pragma unroll
            for (int in = 0; in < 4; in++) {
                int r = wm * 64 + im * 16 + gid;
                int c = wn * 32 + in * 8 + 2 * tig;
                Cs[r * 132 + c]           = acc[im][in][0];
                Cs[r * 132 + c + 1]       = acc[im][in][1];
                Cs[(r + 8) * 132 + c]     = acc[im][in][2];
                Cs[(r + 8) * 132 + c + 1] = acc[im][in][3];
            }
    }
    __syncthreads();

    const bool rope = (which < 2);
    const float qs = (which == 0) ? 0.125f : 1.0f;
    const int h0 = col0 >> 6;
    #pragma unroll 4
    for (int it = 0; it < 64; it++) {
        int e = tid + it * 256;
        int r = e >> 7, c = e & 127;
        int grow = row0 + r;
        int b = grow >> 11, s = grow & 2047;
        int h = h0 + (c >> 6), d = c & 63;
        float val;
        if (rope) {
            float sn = g_sin[(s << 5) + (d & 31)];
            float v0 = Cs[r * 132 + c];
            float vp = Cs[r * 132 + (c ^ 32)];
            val = (d < 32) ? sn * (v0 - vp) : sn * (v0 + vp);
        } else {
            val = Cs[r * 132 + c];
        }
        out[(((b * H + h) * S) + s) * D + d] = f2tf(val * qs);
    }
}

// ---------------------------------------------------------------------------
// Output projection: out = Y @ Wo + bo
// ---------------------------------------------------------------------------
__global__ __launch_bounds__(256) void out_proj_kernel(
    const float* __restrict__ bo, float* __restrict__ out)
{
    extern __shared__ uint32_t sm[];
    const int tid = threadIdx.x;
    const int row0 = blockIdx.y * 128;
    const int col0 = blockIdx.x * 128;

    float acc[4][4][4] = {};
    gemm128(g_Y, g_tf + TF_WO, row0, col0, sm, acc, tid);

    const int lane = tid & 31, warp = tid >> 5;
    const int wm = warp >> 2, wn = warp & 3;
    const int gid = lane >> 2, tig = lane & 3;

    #pragma unroll
    for (int im = 0; im < 4; im++)
        #pragma unroll
        for (int in = 0; in < 4; in++) {
            int r = row0 + wm * 64 + im * 16 + gid;
            int c = col0 + wn * 32 + in * 8 + 2 * tig;
            float b0 = bo[c], b1 = bo[c + 1];
            float2 v0 = make_float2(acc[im][in][0] + b0, acc[im][in][1] + b1);
            float2 v1 = make_float2(acc[im][in][2] + b0, acc[im][in][3] + b1);
            *(float2*)&out[(size_t)r * E + c]       = v0;
            *(float2*)&out[(size_t)(r + 8) * E + c] = v1;
        }
}

// ---------------------------------------------------------------------------
// Flash attention with tf32 tensor cores (inputs already tf32 bits).
// CTA = 128 queries x (b,h). 8 warps, each owns 16 rows. K-tile = 64 keys.
// ---------------------------------------------------------------------------
constexpr int AP = 68;
constexpr int ATTN_SMEM = (128 * AP + 64 * AP + 64 * AP + 128 * AP) * 4;

__global__ __launch_bounds__(256, 1) void attn_kernel()
{
    extern __shared__ uint32_t sm[];
    uint32_t* Qs = sm;                    // [128][AP]
    uint32_t* Ks = Qs + 128 * AP;         // [64][AP]  j-major
    uint32_t* Vt = Ks + 64 * AP;          // [64][AP]  d-major
    uint32_t* Ps = Vt + 64 * AP;          // [128][AP]

    const int qt = (gridDim.x - 1) - blockIdx.x; // heavy tiles first
    const int h = blockIdx.y, b = blockIdx.z;
    const int tid = threadIdx.x;
    const int w = tid >> 5, lane = tid & 31;
    const int gid = lane >> 2, tig = lane & 3;
    const int base = ((b * H + h) * S) * D;
    const int q0 = qt * 128;

    #pragma unroll
    for (int it = 0; it < 32; it++) {
        int idx = tid + it * 256;
        int row = idx >> 6, d = idx & 63;
        Qs[row * AP + d] = g_Q[base + (q0 + row) * D + d];
    }

    const int r0 = w * 16 + gid;
    const int grow0 = q0 + r0;

    float m0 = -1e30f, m1 = -1e30f, l0 = 0.0f, l1 = 0.0f;
    float o[8][4] = {};

    const int NKT = 2 * qt + 2;
    for (int kt = 0; kt < NKT; kt++) {
        __syncthreads();
        const int k0 = kt * 64;
        #pragma unroll
        for (int it = 0; it < 16; it++) {
            int idx = tid + it * 256;
            int j = idx >> 6, d = idx & 63;
            Ks[j * AP + d] = g_K[base + (k0 + j) * D + d];
            Vt[d * AP + j] = g_V[base + (k0 + j) * D + d];
        }
        __syncthreads();

        float sacc[8][4] = {};
        #pragma unroll
        for (int kk = 0; kk < 8; kk++) {
            int d0 = kk * 8;
            uint32_t a0 = Qs[r0 * AP + d0 + tig];
            uint32_t a1 = Qs[(r0 + 8) * AP + d0 + tig];
            uint32_t a2 = Qs[r0 * AP + d0 + tig + 4];
            uint32_t a3 = Qs[(r0 + 8) * AP + d0 + tig + 4];
            #pragma unroll
            for (int in = 0; in < 8; in++) {
                uint32_t b0 = Ks[(in * 8 + gid) * AP + d0 + tig];
                uint32_t b1 = Ks[(in * 8 + gid) * AP + d0 + tig + 4];
                mma_tf32(sacc[in], a0, a1, a2, a3, b0, b1);
            }
        }

        if (kt >= 2 * qt) {
            #pragma unroll
            for (int in = 0; in < 8; in++) {
                int gc = k0 + in * 8 + 2 * tig;
                if (gc     > grow0)     sacc[in][0] = -1e30f;
                if (gc + 1 > grow0)     sacc[in][1] = -1e30f;
                if (gc     > grow0 + 8) sacc[in][2] = -1e30f;
                if (gc + 1 > grow0 + 8) sacc[in][3] = -1e30f;
            }
        }

        float mx0 = -1e30f, mx1 = -1e30f;
        #pragma unroll
        for (int in = 0; in < 8; in++) {
            mx0 = fmaxf(mx0, fmaxf(sacc[in][0], sacc[in][1]));
            mx1 = fmaxf(mx1, fmaxf(sacc[in][2], sacc[in][3]));
        }
        mx0 = fmaxf(mx0, __shfl_xor_sync(0xFFFFFFFFu, mx0, 1));
        mx0 = fmaxf(mx0, __shfl_xor_sync(0xFFFFFFFFu, mx0, 2));
        mx1 = fmaxf(mx1, __shfl_xor_sync(0xFFFFFFFFu, mx1, 1));
        mx1 = fmaxf(mx1, __shfl_xor_sync(0xFFFFFFFFu, mx1, 2));
        float mn0 = fmaxf(m0, mx0), mn1 = fmaxf(m1, mx1);
        float cr0 = __expf(m0 - mn0), cr1 = __expf(m1 - mn1);

        float rs0 = 0.0f, rs1 = 0.0f;
        #pragma unroll
        for (int in = 0; in < 8; in++) {
            float p0 = __expf(sacc[in][0] - mn0);
            float p1 = __expf(sacc[in][1] - mn0);
            float p2 = __expf(sacc[in][2] - mn1);
            float p3 = __expf(sacc[in][3] - mn1);
            rs0 += p0 + p1;
            rs1 += p2 + p3;
            uint2 w0 = make_uint2(f2tf(p0), f2tf(p1));
            uint2 w1 = make_uint2(f2tf(p2), f2tf(p3));
            *(uint2*)&Ps[r0 * AP + in * 8 + 2 * tig]       = w0;
            *(uint2*)&Ps[(r0 + 8) * AP + in * 8 + 2 * tig] = w1;
        }
        rs0 += __shfl_xor_sync(0xFFFFFFFFu, rs0, 1);
        rs0 += __shfl_xor_sync(0xFFFFFFFFu, rs0, 2);
        rs1 += __shfl_xor_sync(0xFFFFFFFFu, rs1, 1);
        rs1 += __shfl_xor_sync(0xFFFFFFFFu, rs1, 2);
        l0 = l0 * cr0 + rs0;
        l1 = l1 * cr1 + rs1;
        m0 = mn0; m1 = mn1;
        #pragma unroll
        for (int in = 0; in < 8; in++) {
            o[in][0] *= cr0; o[in][1] *= cr0;
            o[in][2] *= cr1; o[in][3] *= cr1;
        }
        __syncwarp();

        #pragma unroll
        for (int kk = 0; kk < 8; kk++) {
            int j0 = kk * 8;
            uint32_t a0 = Ps[r0 * AP + j0 + tig];
            uint32_t a1 = Ps[(r0 + 8) * AP + j0 + tig];
            uint32_t a2 = Ps[r0 * AP + j0 + tig + 4];
            uint32_t a3 = Ps[(r0 + 8) * AP + j0 + tig + 4];
            #pragma unroll
            for (int in = 0; in < 8; in++) {
                uint32_t b0 = Vt[(in * 8 + gid) * AP + j0 + tig];
                uint32_t b1 = Vt[(in * 8 + gid) * AP + j0 + tig + 4];
                mma_tf32(o[in], a0, a1, a2, a3, b0, b1);
            }
        }
    }

    // Epilogue: normalize, write Y as tf32 bits in [B, S, H*D]
    float inv0 = 1.0f / l0, inv1 = 1.0f / l1;
    #pragma unroll
    for (int in = 0; in < 8; in++) {
        int c = h * 64 + in * 8 + 2 * tig;
        uint2 v0 = make_uint2(f2tf(o[in][0] * inv0), f2tf(o[in][1] * inv0));
        uint2 v1 = make_uint2(f2tf(o[in][2] * inv1), f2tf(o[in][3] * inv1));
        *(uint2*)&g_Y[(size_t)(b * S + grow0) * E + c]     = v0;
        *(uint2*)&g_Y[(size_t)(b * S + grow0 + 8) * E + c] = v1;
    }
}

// ---------------------------------------------------------------------------
extern "C" void kernel_launch(void* const* d_in, const int* in_sizes, int n_in,
                              void* d_out, int out_size)
{
    (void)in_sizes; (void)n_in; (void)out_size;
    const float* x  = (const float*)d_in[0];
    const float* Wq = (const float*)d_in[1];
    const float* Wk = (const float*)d_in[2];
    const float* Wv = (const float*)d_in[3];
    const float* Wo = (const float*)d_in[4];
    const float* bo = (const float*)d_in[5];
    float* out = (float*)d_out;

    cudaFuncSetAttribute(qkv_kernel,
                         cudaFuncAttributeMaxDynamicSharedMemorySize, QKV_SMEM);
    cudaFuncSetAttribute(out_proj_kernel,
                         cudaFuncAttributeMaxDynamicSharedMemorySize, GEMM_SMEM);
    cudaFuncSetAttribute(attn_kernel,
                         cudaFuncAttributeMaxDynamicSharedMemorySize, ATTN_SMEM);

    sin_kernel<<<(S * 32 + 255) / 256, 256>>>();
    cvt_kernel<<<8 * 1024 * 1024 / (256 * 4), 256>>>(x, Wq, Wk, Wv, Wo);

    dim3 g1(E / 128, M_TOT / 128, 3);
    qkv_kernel<<<g1, 256, QKV_SMEM>>>();

    dim3 g2(S / 128, H, B);
    attn_kernel<<<g2, 256, ATTN_SMEM>>>();

    dim3 g3(E / 128, M_TOT / 128);
    out_proj_kernel<<<g3, 256, GEMM_SMEM>>>(bo, out);
}

// round 6
// speedup vs baseline: 3.2735x; 1.0778x over previous
#include <cuda_runtime.h>
#include <cuda_bf16.h>
#include <cstdint>
#include <math.h>

// Problem constants
constexpr int B = 2, S = 2048, H = 16, D = 64, E = 1024; // E = H*D
constexpr int M_TOT = B * S;                              // 4096

// Scratch (device globals — allocation-free). All hold tf32 bit patterns.
__device__ uint32_t g_Q[(size_t)B * H * S * D];
__device__ uint32_t g_K[(size_t)B * H * S * D];
__device__ uint32_t g_V[(size_t)B * H * S * D];
__device__ uint32_t g_Y[(size_t)M_TOT * E];
// tf32-converted inputs: [X: 0..4M) [Wq: 4M..5M) [Wk: 5M..6M) [Wv: 6M..7M) [Wo: 7M..8M)
constexpr size_t TF_X  = 0;
constexpr size_t TF_WQ = (size_t)4 * 1024 * 1024;
constexpr size_t TF_WK = (size_t)5 * 1024 * 1024;
constexpr size_t TF_WV = (size_t)6 * 1024 * 1024;
constexpr size_t TF_WO = (size_t)7 * 1024 * 1024;
__device__ uint32_t g_tf[(size_t)8 * 1024 * 1024];
__device__ float g_sin[(size_t)S * 32];

// ---------------------------------------------------------------------------
// tf32 helpers
// ---------------------------------------------------------------------------
__device__ __forceinline__ uint32_t f2tf(float f) {
    uint32_t u;
    asm("cvt.rna.tf32.f32 %0, %1;" : "=r"(u) : "f"(f));
    return u;
}

__device__ __forceinline__ void mma_tf32(float c[4],
                                         uint32_t a0, uint32_t a1, uint32_t a2, uint32_t a3,
                                         uint32_t b0, uint32_t b1) {
    asm volatile(
        "mma.sync.aligned.m16n8k8.row.col.f32.tf32.tf32.f32 "
        "{%0,%1,%2,%3},{%4,%5,%6,%7},{%8,%9},{%0,%1,%2,%3};"
        : "+f"(c[0]), "+f"(c[1]), "+f"(c[2]), "+f"(c[3])
        : "r"(a0), "r"(a1), "r"(a2), "r"(a3), "r"(b0), "r"(b1));
}

__device__ __forceinline__ void cp16(uint32_t dst, const uint32_t* src) {
    asm volatile("cp.async.cg.shared.global [%0], [%1], 16;" :: "r"(dst), "l"(src));
}

// ---------------------------------------------------------------------------
// RoPE sin table (reference's c = sin bug replicated)
// ---------------------------------------------------------------------------
__global__ void sin_kernel() {
    int i = blockIdx.x * 256 + threadIdx.x;
    if (i < S * 32) {
        int s = i >> 5, j = i & 31;
        float theta = exp2f(-(float)j * (13.287712379549449f / 16.0f));
        g_sin[i] = sinf((float)s * theta);
    }
}

// ---------------------------------------------------------------------------
// Convert inputs to tf32 bits (8M elements, float4-vectorized)
// ---------------------------------------------------------------------------
__global__ __launch_bounds__(256) void cvt_kernel(
    const float* __restrict__ x,  const float* __restrict__ Wq,
    const float* __restrict__ Wk, const float* __restrict__ Wv,
    const float* __restrict__ Wo)
{
    size_t i = ((size_t)blockIdx.x * 256 + threadIdx.x) * 4;
    const float* src;
    size_t off;
    if (i < TF_WQ)      { src = x;  off = i; }
    else if (i < TF_WK) { src = Wq; off = i - TF_WQ; }
    else if (i < TF_WV) { src = Wk; off = i - TF_WK; }
    else if (i < TF_WO) { src = Wv; off = i - TF_WV; }
    else                { src = Wo; off = i - TF_WO; }
    float4 v = *(const float4*)&src[off];
    uint4 o = make_uint4(f2tf(v.x), f2tf(v.y), f2tf(v.z), f2tf(v.w));
    *(uint4*)&g_tf[i] = o;
}

// ---------------------------------------------------------------------------
// cp.async 4-stage tf32 GEMM mainloop (unchanged from R5)
// ---------------------------------------------------------------------------
constexpr int NSTG = 4;
constexpr int AP_A = 20;
constexpr int AP_B = 136;
constexpr int ASTG_W = 128 * AP_A;
constexpr int BSTG_W = 16 * AP_B;
constexpr int STG_W  = ASTG_W + BSTG_W;
constexpr int GEMM_SMEM = NSTG * STG_W * 4;

__device__ __forceinline__ void gemm_issue(const uint32_t* Ag, const uint32_t* Bg,
                                           int row0, int col0, int k0,
                                           uint32_t abase, uint32_t bbase, int tid)
{
    int r0 = tid >> 2, kq = (tid & 3) * 4;
    cp16(abase + (uint32_t)(r0 * AP_A + kq) * 4,
         Ag + (size_t)(row0 + r0) * E + k0 + kq);
    cp16(abase + (uint32_t)((r0 + 64) * AP_A + kq) * 4,
         Ag + (size_t)(row0 + r0 + 64) * E + k0 + kq);
    int kr = tid >> 5, nq = (tid & 31) * 4;
    cp16(bbase + (uint32_t)(kr * AP_B + nq) * 4,
         Bg + (size_t)(k0 + kr) * E + col0 + nq);
    cp16(bbase + (uint32_t)((kr + 8) * AP_B + nq) * 4,
         Bg + (size_t)(k0 + kr + 8) * E + col0 + nq);
}

__device__ __forceinline__ void gemm_mma(const uint32_t* a, const uint32_t* b,
                                         float (&acc)[4][4][4],
                                         int wm, int wn, int gid, int tig)
{
    #pragma unroll
    for (int kk = 0; kk < 2; kk++) {
        int kc = kk * 8;
        uint32_t af[4][4], bf[4][2];
        #pragma unroll
        for (int im = 0; im < 4; im++) {
            int mb = wm * 64 + im * 16 + gid;
            af[im][0] = a[mb * AP_A + kc + tig];
            af[im][1] = a[(mb + 8) * AP_A + kc + tig];
            af[im][2] = a[mb * AP_A + kc + tig + 4];
            af[im][3] = a[(mb + 8) * AP_A + kc + tig + 4];
        }
        #pragma unroll
        for (int in = 0; in < 4; in++) {
            int nb = wn * 32 + in * 8 + gid;
            bf[in][0] = b[(kc + tig) * AP_B + nb];
            bf[in][1] = b[(kc + tig + 4) * AP_B + nb];
        }
        #pragma unroll
        for (int im = 0; im < 4; im++)
            #pragma unroll
            for (int in = 0; in < 4; in++)
                mma_tf32(acc[im][in], af[im][0], af[im][1], af[im][2], af[im][3],
                         bf[in][0], bf[in][1]);
    }
}

__device__ __forceinline__ void gemm128(const uint32_t* __restrict__ Ag,
                                        const uint32_t* __restrict__ Bg,
                                        int row0, int col0,
                                        uint32_t* sm, float (&acc)[4][4][4], int tid)
{
    const int lane = tid & 31, warp = tid >> 5;
    const int wm = warp >> 2, wn = warp & 3;
    const int gid = lane >> 2, tig = lane & 3;

    uint32_t smbase = (uint32_t)__cvta_generic_to_shared(sm);

    #pragma unroll
    for (int p = 0; p < 3; p++) {
        uint32_t ab = smbase + (uint32_t)(p * STG_W) * 4;
        gemm_issue(Ag, Bg, row0, col0, p * 16, ab, ab + ASTG_W * 4, tid);
        asm volatile("cp.async.commit_group;" ::: "memory");
    }

    const int NS = E / 16;
    for (int s = 0; s < NS; s++) {
        asm volatile("cp.async.wait_group 2;" ::: "memory");
        __syncthreads();
        if (s + 3 < NS) {
            int st = (s + 3) & 3;
            uint32_t ab = smbase + (uint32_t)(st * STG_W) * 4;
            gemm_issue(Ag, Bg, row0, col0, (s + 3) * 16, ab, ab + ASTG_W * 4, tid);
        }
        asm volatile("cp.async.commit_group;" ::: "memory");
        int cur = s & 3;
        gemm_mma(sm + cur * STG_W, sm + cur * STG_W + ASTG_W, acc, wm, wn, gid, tig);
    }
}

// ---------------------------------------------------------------------------
// QKV projection + fused RoPE epilogue (unchanged from R5)
// ---------------------------------------------------------------------------
constexpr int QKV_SMEM = (GEMM_SMEM > 128 * 132 * 4) ? GEMM_SMEM : 128 * 132 * 4;

__global__ __launch_bounds__(256) void qkv_kernel()
{
    extern __shared__ uint32_t sm[];
    const int which = blockIdx.z;
    const uint32_t* W = g_tf + ((which == 0) ? TF_WQ : (which == 1) ? TF_WK : TF_WV);
    uint32_t* out = (which == 0) ? g_Q : (which == 1) ? g_K : g_V;

    const int tid = threadIdx.x;
    const int row0 = blockIdx.y * 128;
    const int col0 = blockIdx.x * 128;

    float acc[4][4][4] = {};
    gemm128(g_tf + TF_X, W, row0, col0, sm, acc, tid);
    __syncthreads();

    float* Cs = (float*)sm; // [128][132]
    {
        const int lane = tid & 31, warp = tid >> 5;
        const int wm = warp >> 2, wn = warp & 3;
        const int gid = lane >> 2, tig = lane & 3;
        #pragma unroll
        for (int im = 0; im < 4; im++)
            #pragma unroll
            for (int in = 0; in < 4; in++) {
                int r = wm * 64 + im * 16 + gid;
                int c = wn * 32 + in * 8 + 2 * tig;
                Cs[r * 132 + c]           = acc[im][in][0];
                Cs[r * 132 + c + 1]       = acc[im][in][1];
                Cs[(r + 8) * 132 + c]     = acc[im][in][2];
                Cs[(r + 8) * 132 + c + 1] = acc[im][in][3];
            }
    }
    __syncthreads();

    const bool rope = (which < 2);
    const float qs = (which == 0) ? 0.125f : 1.0f;
    const int h0 = col0 >> 6;
    #pragma unroll 4
    for (int it = 0; it < 64; it++) {
        int e = tid + it * 256;
        int r = e >> 7, c = e & 127;
        int grow = row0 + r;
        int b = grow >> 11, s = grow & 2047;
        int h = h0 + (c >> 6), d = c & 63;
        float val;
        if (rope) {
            float sn = g_sin[(s << 5) + (d & 31)];
            float v0 = Cs[r * 132 + c];
            float vp = Cs[r * 132 + (c ^ 32)];
            val = (d < 32) ? sn * (v0 - vp) : sn * (v0 + vp);
        } else {
            val = Cs[r * 132 + c];
        }
        out[(((b * H + h) * S) + s) * D + d] = f2tf(val * qs);
    }
}

// ---------------------------------------------------------------------------
// Output projection (unchanged from R5)
// ---------------------------------------------------------------------------
__global__ __launch_bounds__(256) void out_proj_kernel(
    const float* __restrict__ bo, float* __restrict__ out)
{
    extern __shared__ uint32_t sm[];
    const int tid = threadIdx.x;
    const int row0 = blockIdx.y * 128;
    const int col0 = blockIdx.x * 128;

    float acc[4][4][4] = {};
    gemm128(g_Y, g_tf + TF_WO, row0, col0, sm, acc, tid);

    const int lane = tid & 31, warp = tid >> 5;
    const int wm = warp >> 2, wn = warp & 3;
    const int gid = lane >> 2, tig = lane & 3;

    #pragma unroll
    for (int im = 0; im < 4; im++)
        #pragma unroll
        for (int in = 0; in < 4; in++) {
            int r = row0 + wm * 64 + im * 16 + gid;
            int c = col0 + wn * 32 + in * 8 + 2 * tig;
            float b0 = bo[c], b1 = bo[c + 1];
            float2 v0 = make_float2(acc[im][in][0] + b0, acc[im][in][1] + b1);
            float2 v1 = make_float2(acc[im][in][2] + b0, acc[im][in][3] + b1);
            *(float2*)&out[(size_t)r * E + c]       = v0;
            *(float2*)&out[(size_t)(r + 8) * E + c] = v1;
        }
}

// ---------------------------------------------------------------------------
// Flash attention, tf32 mma, cp.async double-buffered K/V.
// CTA = 128 queries x (b,h). 8 warps x 16 rows. K-tile = 64 keys.
// Ks: [2][64][68] j-major. Vs: [2][64][72] j-major (pitch 72 -> conflict-free
// B-fragment reads: bank = 8*tig + gid, all distinct).
// ---------------------------------------------------------------------------
constexpr int AP = 68;               // pitch for Qs/Ks/Ps
constexpr int VP = 72;               // pitch for Vs
constexpr int KSTG = 64 * AP;        // words per K stage
constexpr int VSTG = 64 * VP;        // words per V stage
constexpr int ATTN_SMEM = (128 * AP + 2 * KSTG + 2 * VSTG + 128 * AP) * 4; // 141312 B

__global__ __launch_bounds__(256, 1) void attn_kernel()
{
    extern __shared__ uint32_t sm[];
    uint32_t* Qs = sm;                     // [128][AP]
    uint32_t* Ks = Qs + 128 * AP;          // [2][64][AP]
    uint32_t* Vs = Ks + 2 * KSTG;          // [2][64][VP]
    uint32_t* Ps = Vs + 2 * VSTG;          // [128][AP]

    const int qt = (gridDim.x - 1) - blockIdx.x; // heavy tiles first
    const int h = blockIdx.y, b = blockIdx.z;
    const int tid = threadIdx.x;
    const int w = tid >> 5, lane = tid & 31;
    const int gid = lane >> 2, tig = lane & 3;
    const int base = ((b * H + h) * S) * D;
    const int q0 = qt * 128;

    const uint32_t ksb = (uint32_t)__cvta_generic_to_shared(Ks);
    const uint32_t vsb = (uint32_t)__cvta_generic_to_shared(Vs);

    // cp.async issue of one K/V tile into buffer `buf`
    auto issue_kv = [&](int k0, int buf) {
        #pragma unroll
        for (int i = 0; i < 4; i++) {
            int f = tid + i * 256;          // float4 index 0..1023
            int j = f >> 4, dq = (f & 15) * 4;
            cp16(ksb + (uint32_t)(buf * KSTG + j * AP + dq) * 4,
                 g_K + base + (k0 + j) * D + dq);
            cp16(vsb + (uint32_t)(buf * VSTG + j * VP + dq) * 4,
                 g_V + base + (k0 + j) * D + dq);
        }
        asm volatile("cp.async.commit_group;" ::: "memory");
    };

    // Prefetch tile 0, then load Q (overlaps with cp.async)
    issue_kv(0, 0);
    #pragma unroll
    for (int it = 0; it < 8; it++) {
        int f = tid + it * 256;             // float4 index 0..2047
        int row = f >> 4, dq = (f & 15) * 4;
        uint4 v = *(const uint4*)&g_Q[base + (q0 + row) * D + dq];
        *(uint4*)&Qs[row * AP + dq] = v;
    }

    const int r0 = w * 16 + gid;
    const int grow0 = q0 + r0;

    float m0 = -1e30f, m1 = -1e30f, l0 = 0.0f, l1 = 0.0f;
    float o[8][4] = {};

    const int NKT = 2 * qt + 2;
    for (int kt = 0; kt < NKT; kt++) {
        const int cur = kt & 1, nxt = cur ^ 1;
        __syncthreads(); // prev mma reads of buffer `nxt` done (Q/P reads too)
        if (kt + 1 < NKT) issue_kv((kt + 1) * 64, nxt);
        else asm volatile("cp.async.commit_group;" ::: "memory");
        asm volatile("cp.async.wait_group 1;" ::: "memory"); // tile kt resident
        __syncthreads();

        const uint32_t* Kc = Ks + cur * KSTG;
        const uint32_t* Vc = Vs + cur * VSTG;
        const int k0 = kt * 64;

        // S = Q @ K^T
        float sacc[8][4] = {};
        #pragma unroll
        for (int kk = 0; kk < 8; kk++) {
            int d0 = kk * 8;
            uint32_t a0 = Qs[r0 * AP + d0 + tig];
            uint32_t a1 = Qs[(r0 + 8) * AP + d0 + tig];
            uint32_t a2 = Qs[r0 * AP + d0 + tig + 4];
            uint32_t a3 = Qs[(r0 + 8) * AP + d0 + tig + 4];
            #pragma unroll
            for (int in = 0; in < 8; in++) {
                uint32_t b0 = Kc[(in * 8 + gid) * AP + d0 + tig];
                uint32_t b1 = Kc[(in * 8 + gid) * AP + d0 + tig + 4];
                mma_tf32(sacc[in], a0, a1, a2, a3, b0, b1);
            }
        }

        // Causal mask (only the last two k-tiles cross the diagonal)
        if (kt >= 2 * qt) {
            #pragma unroll
            for (int in = 0; in < 8; in++) {
                int gc = k0 + in * 8 + 2 * tig;
                if (gc     > grow0)     sacc[in][0] = -1e30f;
                if (gc + 1 > grow0)     sacc[in][1] = -1e30f;
                if (gc     > grow0 + 8) sacc[in][2] = -1e30f;
                if (gc + 1 > grow0 + 8) sacc[in][3] = -1e30f;
            }
        }

        // Online softmax (rows r0, r0+8; reduce over the 4 tig lanes)
        float mx0 = -1e30f, mx1 = -1e30f;
        #pragma unroll
        for (int in = 0; in < 8; in++) {
            mx0 = fmaxf(mx0, fmaxf(sacc[in][0], sacc[in][1]));
            mx1 = fmaxf(mx1, fmaxf(sacc[in][2], sacc[in][3]));
        }
        mx0 = fmaxf(mx0, __shfl_xor_sync(0xFFFFFFFFu, mx0, 1));
        mx0 = fmaxf(mx0, __shfl_xor_sync(0xFFFFFFFFu, mx0, 2));
        mx1 = fmaxf(mx1, __shfl_xor_sync(0xFFFFFFFFu, mx1, 1));
        mx1 = fmaxf(mx1, __shfl_xor_sync(0xFFFFFFFFu, mx1, 2));
        float mn0 = fmaxf(m0, mx0), mn1 = fmaxf(m1, mx1);
        float cr0 = __expf(m0 - mn0), cr1 = __expf(m1 - mn1);

        float rs0 = 0.0f, rs1 = 0.0f;
        #pragma unroll
        for (int in = 0; in < 8; in++) {
            float p0 = __expf(sacc[in][0] - mn0);
            float p1 = __expf(sacc[in][1] - mn0);
            float p2 = __expf(sacc[in][2] - mn1);
            float p3 = __expf(sacc[in][3] - mn1);
            rs0 += p0 + p1;
            rs1 += p2 + p3;
            uint2 w0 = make_uint2(f2tf(p0), f2tf(p1));
            uint2 w1 = make_uint2(f2tf(p2), f2tf(p3));
            *(uint2*)&Ps[r0 * AP + in * 8 + 2 * tig]       = w0;
            *(uint2*)&Ps[(r0 + 8) * AP + in * 8 + 2 * tig] = w1;
        }
        rs0 += __shfl_xor_sync(0xFFFFFFFFu, rs0, 1);
        rs0 += __shfl_xor_sync(0xFFFFFFFFu, rs0, 2);
        rs1 += __shfl_xor_sync(0xFFFFFFFFu, rs1, 1);
        rs1 += __shfl_xor_sync(0xFFFFFFFFu, rs1, 2);
        l0 = l0 * cr0 + rs0;
        l1 = l1 * cr1 + rs1;
        m0 = mn0; m1 = mn1;
        #pragma unroll
        for (int in = 0; in < 8; in++) {
            o[in][0] *= cr0; o[in][1] *= cr0;
            o[in][2] *= cr1; o[in][3] *= cr1;
        }
        __syncwarp(); // warp's own P rows

        // O += P @ V   (V j-major, pitch 72 -> conflict-free B fragments)
        #pragma unroll
        for (int kk = 0; kk < 8; kk++) {
            int j0 = kk * 8;
            uint32_t a0 = Ps[r0 * AP + j0 + tig];
            uint32_t a1 = Ps[(r0 + 8) * AP + j0 + tig];
            uint32_t a2 = Ps[r0 * AP + j0 + tig + 4];
            uint32_t a3 = Ps[(r0 + 8) * AP + j0 + tig + 4];
            #pragma unroll
            for (int in = 0; in < 8; in++) {
                uint32_t b0 = Vc[(j0 + tig) * VP + in * 8 + gid];
                uint32_t b1 = Vc[(j0 + tig + 4) * VP + in * 8 + gid];
                mma_tf32(o[in], a0, a1, a2, a3, b0, b1);
            }
        }
    }

    // Epilogue: normalize, write Y as tf32 bits in [B, S, H*D]
    float inv0 = 1.0f / l0, inv1 = 1.0f / l1;
    #pragma unroll
    for (int in = 0; in < 8; in++) {
        int c = h * 64 + in * 8 + 2 * tig;
        uint2 v0 = make_uint2(f2tf(o[in][0] * inv0), f2tf(o[in][1] * inv0));
        uint2 v1 = make_uint2(f2tf(o[in][2] * inv1), f2tf(o[in][3] * inv1));
        *(uint2*)&g_Y[(size_t)(b * S + grow0) * E + c]     = v0;
        *(uint2*)&g_Y[(size_t)(b * S + grow0 + 8) * E + c] = v1;
    }
}

// ---------------------------------------------------------------------------
extern "C" void kernel_launch(void* const* d_in, const int* in_sizes, int n_in,
                              void* d_out, int out_size)
{
    (void)in_sizes; (void)n_in; (void)out_size;
    const float* x  = (const float*)d_in[0];
    const float* Wq = (const float*)d_in[1];
    const float* Wk = (const float*)d_in[2];
    const float* Wv = (const float*)d_in[3];
    const float* Wo = (const float*)d_in[4];
    const float* bo = (const float*)d_in[5];
    float* out = (float*)d_out;

    cudaFuncSetAttribute(qkv_kernel,
                         cudaFuncAttributeMaxDynamicSharedMemorySize, QKV_SMEM);
    cudaFuncSetAttribute(out_proj_kernel,
                         cudaFuncAttributeMaxDynamicSharedMemorySize, GEMM_SMEM);
    cudaFuncSetAttribute(attn_kernel,
                         cudaFuncAttributeMaxDynamicSharedMemorySize, ATTN_SMEM);

    sin_kernel<<<(S * 32 + 255) / 256, 256>>>();
    cvt_kernel<<<8 * 1024 * 1024 / (256 * 4), 256>>>(x, Wq, Wk, Wv, Wo);

    dim3 g1(E / 128, M_TOT / 128, 3);
    qkv_kernel<<<g1, 256, QKV_SMEM>>>();

    dim3 g2(S / 128, H, B);
    attn_kernel<<<g2, 256, ATTN_SMEM>>>();

    dim3 g3(E / 128, M_TOT / 128);
    out_proj_kernel<<<g3, 256, GEMM_SMEM>>>(bo, out);
}

// round 7
// speedup vs baseline: 3.3155x; 1.0128x over previous
#include <cuda_runtime.h>
#include <cuda_bf16.h>
#include <cstdint>
#include <math.h>

// Problem constants
constexpr int B = 2, S = 2048, H = 16, D = 64, E = 1024; // E = H*D
constexpr int M_TOT = B * S;                              // 4096

// Scratch (device globals — allocation-free). All hold tf32 bit patterns.
__device__ uint32_t g_Q[(size_t)B * H * S * D];
__device__ uint32_t g_K[(size_t)B * H * S * D];
__device__ uint32_t g_V[(size_t)B * H * S * D];
__device__ uint32_t g_Y[(size_t)M_TOT * E];
// tf32-converted inputs: [X: 0..4M) [Wq: 4M..5M) [Wk: 5M..6M) [Wv: 6M..7M) [Wo: 7M..8M)
constexpr size_t TF_X  = 0;
constexpr size_t TF_WQ = (size_t)4 * 1024 * 1024;
constexpr size_t TF_WK = (size_t)5 * 1024 * 1024;
constexpr size_t TF_WV = (size_t)6 * 1024 * 1024;
constexpr size_t TF_WO = (size_t)7 * 1024 * 1024;
__device__ uint32_t g_tf[(size_t)8 * 1024 * 1024];
__device__ float g_sin[(size_t)S * 32];

// ---------------------------------------------------------------------------
// tf32 helpers
// ---------------------------------------------------------------------------
__device__ __forceinline__ uint32_t f2tf(float f) {
    uint32_t u;
    asm("cvt.rna.tf32.f32 %0, %1;" : "=r"(u) : "f"(f));
    return u;
}

__device__ __forceinline__ void mma_tf32(float c[4],
                                         uint32_t a0, uint32_t a1, uint32_t a2, uint32_t a3,
                                         uint32_t b0, uint32_t b1) {
    asm volatile(
        "mma.sync.aligned.m16n8k8.row.col.f32.tf32.tf32.f32 "
        "{%0,%1,%2,%3},{%4,%5,%6,%7},{%8,%9},{%0,%1,%2,%3};"
        : "+f"(c[0]), "+f"(c[1]), "+f"(c[2]), "+f"(c[3])
        : "r"(a0), "r"(a1), "r"(a2), "r"(a3), "r"(b0), "r"(b1));
}

__device__ __forceinline__ void cp16(uint32_t dst, const uint32_t* src) {
    asm volatile("cp.async.cg.shared.global [%0], [%1], 16;" :: "r"(dst), "l"(src));
}

// ---------------------------------------------------------------------------
// RoPE sin table (reference's c = sin bug replicated)
// ---------------------------------------------------------------------------
__global__ void sin_kernel() {
    int i = blockIdx.x * 256 + threadIdx.x;
    if (i < S * 32) {
        int s = i >> 5, j = i & 31;
        float theta = exp2f(-(float)j * (13.287712379549449f / 16.0f));
        g_sin[i] = sinf((float)s * theta);
    }
}

// ---------------------------------------------------------------------------
// Convert inputs to tf32 bits
// ---------------------------------------------------------------------------
__global__ __launch_bounds__(256) void cvt_kernel(
    const float* __restrict__ x,  const float* __restrict__ Wq,
    const float* __restrict__ Wk, const float* __restrict__ Wv,
    const float* __restrict__ Wo)
{
    size_t i = ((size_t)blockIdx.x * 256 + threadIdx.x) * 4;
    const float* src;
    size_t off;
    if (i < TF_WQ)      { src = x;  off = i; }
    else if (i < TF_WK) { src = Wq; off = i - TF_WQ; }
    else if (i < TF_WV) { src = Wk; off = i - TF_WK; }
    else if (i < TF_WO) { src = Wv; off = i - TF_WV; }
    else                { src = Wo; off = i - TF_WO; }
    float4 v = *(const float4*)&src[off];
    uint4 o = make_uint4(f2tf(v.x), f2tf(v.y), f2tf(v.z), f2tf(v.w));
    *(uint4*)&g_tf[i] = o;
}

// ---------------------------------------------------------------------------
// cp.async 4-stage tf32 GEMM mainloop (unchanged from R6)
// ---------------------------------------------------------------------------
constexpr int NSTG = 4;
constexpr int AP_A = 20;
constexpr int AP_B = 136;
constexpr int ASTG_W = 128 * AP_A;
constexpr int BSTG_W = 16 * AP_B;
constexpr int STG_W  = ASTG_W + BSTG_W;
constexpr int GEMM_SMEM = NSTG * STG_W * 4;

__device__ __forceinline__ void gemm_issue(const uint32_t* Ag, const uint32_t* Bg,
                                           int row0, int col0, int k0,
                                           uint32_t abase, uint32_t bbase, int tid)
{
    int r0 = tid >> 2, kq = (tid & 3) * 4;
    cp16(abase + (uint32_t)(r0 * AP_A + kq) * 4,
         Ag + (size_t)(row0 + r0) * E + k0 + kq);
    cp16(abase + (uint32_t)((r0 + 64) * AP_A + kq) * 4,
         Ag + (size_t)(row0 + r0 + 64) * E + k0 + kq);
    int kr = tid >> 5, nq = (tid & 31) * 4;
    cp16(bbase + (uint32_t)(kr * AP_B + nq) * 4,
         Bg + (size_t)(k0 + kr) * E + col0 + nq);
    cp16(bbase + (uint32_t)((kr + 8) * AP_B + nq) * 4,
         Bg + (size_t)(k0 + kr + 8) * E + col0 + nq);
}

__device__ __forceinline__ void gemm_mma(const uint32_t* a, const uint32_t* b,
                                         float (&acc)[4][4][4],
                                         int wm, int wn, int gid, int tig)
{
    #pragma unroll
    for (int kk = 0; kk < 2; kk++) {
        int kc = kk * 8;
        uint32_t af[4][4], bf[4][2];
        #pragma unroll
        for (int im = 0; im < 4; im++) {
            int mb = wm * 64 + im * 16 + gid;
            af[im][0] = a[mb * AP_A + kc + tig];
            af[im][1] = a[(mb + 8) * AP_A + kc + tig];
            af[im][2] = a[mb * AP_A + kc + tig + 4];
            af[im][3] = a[(mb + 8) * AP_A + kc + tig + 4];
        }
        #pragma unroll
        for (int in = 0; in < 4; in++) {
            int nb = wn * 32 + in * 8 + gid;
            bf[in][0] = b[(kc + tig) * AP_B + nb];
            bf[in][1] = b[(kc + tig + 4) * AP_B + nb];
        }
        #pragma unroll
        for (int im = 0; im < 4; im++)
            #pragma unroll
            for (int in = 0; in < 4; in++)
                mma_tf32(acc[im][in], af[im][0], af[im][1], af[im][2], af[im][3],
                         bf[in][0], bf[in][1]);
    }
}

__device__ __forceinline__ void gemm128(const uint32_t* __restrict__ Ag,
                                        const uint32_t* __restrict__ Bg,
                                        int row0, int col0,
                                        uint32_t* sm, float (&acc)[4][4][4], int tid)
{
    const int lane = tid & 31, warp = tid >> 5;
    const int wm = warp >> 2, wn = warp & 3;
    const int gid = lane >> 2, tig = lane & 3;

    uint32_t smbase = (uint32_t)__cvta_generic_to_shared(sm);

    #pragma unroll
    for (int p = 0; p < 3; p++) {
        uint32_t ab = smbase + (uint32_t)(p * STG_W) * 4;
        gemm_issue(Ag, Bg, row0, col0, p * 16, ab, ab + ASTG_W * 4, tid);
        asm volatile("cp.async.commit_group;" ::: "memory");
    }

    const int NS = E / 16;
    for (int s = 0; s < NS; s++) {
        asm volatile("cp.async.wait_group 2;" ::: "memory");
        __syncthreads();
        if (s + 3 < NS) {
            int st = (s + 3) & 3;
            uint32_t ab = smbase + (uint32_t)(st * STG_W) * 4;
            gemm_issue(Ag, Bg, row0, col0, (s + 3) * 16, ab, ab + ASTG_W * 4, tid);
        }
        asm volatile("cp.async.commit_group;" ::: "memory");
        int cur = s & 3;
        gemm_mma(sm + cur * STG_W, sm + cur * STG_W + ASTG_W, acc, wm, wn, gid, tig);
    }
}

// ---------------------------------------------------------------------------
// QKV projection + fused RoPE epilogue (unchanged from R6)
// ---------------------------------------------------------------------------
constexpr int QKV_SMEM = (GEMM_SMEM > 128 * 132 * 4) ? GEMM_SMEM : 128 * 132 * 4;

__global__ __launch_bounds__(256) void qkv_kernel()
{
    extern __shared__ uint32_t sm[];
    const int which = blockIdx.z;
    const uint32_t* W = g_tf + ((which == 0) ? TF_WQ : (which == 1) ? TF_WK : TF_WV);
    uint32_t* out = (which == 0) ? g_Q : (which == 1) ? g_K : g_V;

    const int tid = threadIdx.x;
    const int row0 = blockIdx.y * 128;
    const int col0 = blockIdx.x * 128;

    float acc[4][4][4] = {};
    gemm128(g_tf + TF_X, W, row0, col0, sm, acc, tid);
    __syncthreads();

    float* Cs = (float*)sm; // [128][132]
    {
        const int lane = tid & 31, warp = tid >> 5;
        const int wm = warp >> 2, wn = warp & 3;
        const int gid = lane >> 2, tig = lane & 3;
        #pragma unroll
        for (int im = 0; im < 4; im++)
            #pragma unroll
            for (int in = 0; in < 4; in++) {
                int r = wm * 64 + im * 16 + gid;
                int c = wn * 32 + in * 8 + 2 * tig;
                Cs[r * 132 + c]           = acc[im][in][0];
                Cs[r * 132 + c + 1]       = acc[im][in][1];
                Cs[(r + 8) * 132 + c]     = acc[im][in][2];
                Cs[(r + 8) * 132 + c + 1] = acc[im][in][3];
            }
    }
    __syncthreads();

    const bool rope = (which < 2);
    const float qs = (which == 0) ? 0.125f : 1.0f;
    const int h0 = col0 >> 6;
    #pragma unroll 4
    for (int it = 0; it < 64; it++) {
        int e = tid + it * 256;
        int r = e >> 7, c = e & 127;
        int grow = row0 + r;
        int b = grow >> 11, s = grow & 2047;
        int h = h0 + (c >> 6), d = c & 63;
        float val;
        if (rope) {
            float sn = g_sin[(s << 5) + (d & 31)];
            float v0 = Cs[r * 132 + c];
            float vp = Cs[r * 132 + (c ^ 32)];
            val = (d < 32) ? sn * (v0 - vp) : sn * (v0 + vp);
        } else {
            val = Cs[r * 132 + c];
        }
        out[(((b * H + h) * S) + s) * D + d] = f2tf(val * qs);
    }
}

// ---------------------------------------------------------------------------
// Output projection (unchanged from R6)
// ---------------------------------------------------------------------------
__global__ __launch_bounds__(256) void out_proj_kernel(
    const float* __restrict__ bo, float* __restrict__ out)
{
    extern __shared__ uint32_t sm[];
    const int tid = threadIdx.x;
    const int row0 = blockIdx.y * 128;
    const int col0 = blockIdx.x * 128;

    float acc[4][4][4] = {};
    gemm128(g_Y, g_tf + TF_WO, row0, col0, sm, acc, tid);

    const int lane = tid & 31, warp = tid >> 5;
    const int wm = warp >> 2, wn = warp & 3;
    const int gid = lane >> 2, tig = lane & 3;

    #pragma unroll
    for (int im = 0; im < 4; im++)
        #pragma unroll
        for (int in = 0; in < 4; in++) {
            int r = row0 + wm * 64 + im * 16 + gid;
            int c = col0 + wn * 32 + in * 8 + 2 * tig;
            float b0 = bo[c], b1 = bo[c + 1];
            float2 v0 = make_float2(acc[im][in][0] + b0, acc[im][in][1] + b1);
            float2 v1 = make_float2(acc[im][in][2] + b0, acc[im][in][3] + b1);
            *(float2*)&out[(size_t)r * E + c]       = v0;
            *(float2*)&out[(size_t)(r + 8) * E + c] = v1;
        }
}

// ---------------------------------------------------------------------------
// Flash attention, tf32 mma, cp.async double-buffered K/V, NO P smem buffer:
// P is redistributed from accumulator layout to A-fragment layout via warp
// shuffles. smem = Qs + 2xK + 2xV = 106496 B -> 2 CTAs/SM.
// ---------------------------------------------------------------------------
constexpr int AP = 68;               // pitch for Qs/Ks
constexpr int VP = 72;               // pitch for Vs
constexpr int KSTG = 64 * AP;
constexpr int VSTG = 64 * VP;
constexpr int ATTN_SMEM = (128 * AP + 2 * KSTG + 2 * VSTG) * 4; // 106496 B

__global__ __launch_bounds__(256, 2) void attn_kernel()
{
    extern __shared__ uint32_t sm[];
    uint32_t* Qs = sm;                     // [128][AP]
    uint32_t* Ks = Qs + 128 * AP;          // [2][64][AP]
    uint32_t* Vs = Ks + 2 * KSTG;          // [2][64][VP]

    const int qt = (gridDim.x - 1) - blockIdx.x; // heavy tiles first
    const int h = blockIdx.y, b = blockIdx.z;
    const int tid = threadIdx.x;
    const int w = tid >> 5, lane = tid & 31;
    const int gid = lane >> 2, tig = lane & 3;
    const int base = ((b * H + h) * S) * D;
    const int q0 = qt * 128;

    const uint32_t ksb = (uint32_t)__cvta_generic_to_shared(Ks);
    const uint32_t vsb = (uint32_t)__cvta_generic_to_shared(Vs);

    auto issue_kv = [&](int k0, int buf) {
        #pragma unroll
        for (int i = 0; i < 4; i++) {
            int f = tid + i * 256;
            int j = f >> 4, dq = (f & 15) * 4;
            cp16(ksb + (uint32_t)(buf * KSTG + j * AP + dq) * 4,
                 g_K + base + (k0 + j) * D + dq);
            cp16(vsb + (uint32_t)(buf * VSTG + j * VP + dq) * 4,
                 g_V + base + (k0 + j) * D + dq);
        }
        asm volatile("cp.async.commit_group;" ::: "memory");
    };

    issue_kv(0, 0);
    #pragma unroll
    for (int it = 0; it < 8; it++) {
        int f = tid + it * 256;
        int row = f >> 4, dq = (f & 15) * 4;
        uint4 v = *(const uint4*)&g_Q[base + (q0 + row) * D + dq];
        *(uint4*)&Qs[row * AP + dq] = v;
    }

    const int r0 = w * 16 + gid;
    const int grow0 = q0 + r0;
    const int psrc0 = 4 * gid + (tig >> 1);  // shfl source lane for P cols tig
    const int psrc1 = psrc0 + 2;             // ... for P cols tig+4
    const bool podd = (tig & 1);

    float m0 = -1e30f, m1 = -1e30f, l0 = 0.0f, l1 = 0.0f;
    float o[8][4] = {};

    const int NKT = 2 * qt + 2;
    for (int kt = 0; kt < NKT; kt++) {
        const int cur = kt & 1, nxt = cur ^ 1;
        __syncthreads(); // all warps done reading buffer `nxt` from iter kt-1
        if (kt + 1 < NKT) issue_kv((kt + 1) * 64, nxt);
        else asm volatile("cp.async.commit_group;" ::: "memory");
        asm volatile("cp.async.wait_group 1;" ::: "memory");
        __syncthreads();

        const uint32_t* Kc = Ks + cur * KSTG;
        const uint32_t* Vc = Vs + cur * VSTG;
        const int k0 = kt * 64;

        // S = Q @ K^T
        float sacc[8][4] = {};
        #pragma unroll
        for (int kk = 0; kk < 8; kk++) {
            int d0 = kk * 8;
            uint32_t a0 = Qs[r0 * AP + d0 + tig];
            uint32_t a1 = Qs[(r0 + 8) * AP + d0 + tig];
            uint32_t a2 = Qs[r0 * AP + d0 + tig + 4];
            uint32_t a3 = Qs[(r0 + 8) * AP + d0 + tig + 4];
            #pragma unroll
            for (int in = 0; in < 8; in++) {
                uint32_t b0 = Kc[(in * 8 + gid) * AP + d0 + tig];
                uint32_t b1 = Kc[(in * 8 + gid) * AP + d0 + tig + 4];
                mma_tf32(sacc[in], a0, a1, a2, a3, b0, b1);
            }
        }

        // Causal mask (only the last two k-tiles cross the diagonal)
        if (kt >= 2 * qt) {
            #pragma unroll
            for (int in = 0; in < 8; in++) {
                int gc = k0 + in * 8 + 2 * tig;
                if (gc     > grow0)     sacc[in][0] = -1e30f;
                if (gc + 1 > grow0)     sacc[in][1] = -1e30f;
                if (gc     > grow0 + 8) sacc[in][2] = -1e30f;
                if (gc + 1 > grow0 + 8) sacc[in][3] = -1e30f;
            }
        }

        // Online softmax (rows r0, r0+8; reduce over the 4 tig lanes)
        float mx0 = -1e30f, mx1 = -1e30f;
        #pragma unroll
        for (int in = 0; in < 8; in++) {
            mx0 = fmaxf(mx0, fmaxf(sacc[in][0], sacc[in][1]));
            mx1 = fmaxf(mx1, fmaxf(sacc[in][2], sacc[in][3]));
        }
        mx0 = fmaxf(mx0, __shfl_xor_sync(0xFFFFFFFFu, mx0, 1));
        mx0 = fmaxf(mx0, __shfl_xor_sync(0xFFFFFFFFu, mx0, 2));
        mx1 = fmaxf(mx1, __shfl_xor_sync(0xFFFFFFFFu, mx1, 1));
        mx1 = fmaxf(mx1, __shfl_xor_sync(0xFFFFFFFFu, mx1, 2));
        float mn0 = fmaxf(m0, mx0), mn1 = fmaxf(m1, mx1);
        float cr0 = __expf(m0 - mn0), cr1 = __expf(m1 - mn1);

        float rs0 = 0.0f, rs1 = 0.0f;
        #pragma unroll
        for (int in = 0; in < 8; in++) {
            sacc[in][0] = __expf(sacc[in][0] - mn0);
            sacc[in][1] = __expf(sacc[in][1] - mn0);
            sacc[in][2] = __expf(sacc[in][2] - mn1);
            sacc[in][3] = __expf(sacc[in][3] - mn1);
            rs0 += sacc[in][0] + sacc[in][1];
            rs1 += sacc[in][2] + sacc[in][3];
        }
        rs0 += __shfl_xor_sync(0xFFFFFFFFu, rs0, 1);
        rs0 += __shfl_xor_sync(0xFFFFFFFFu, rs0, 2);
        rs1 += __shfl_xor_sync(0xFFFFFFFFu, rs1, 1);
        rs1 += __shfl_xor_sync(0xFFFFFFFFu, rs1, 2);
        l0 = l0 * cr0 + rs0;
        l1 = l1 * cr1 + rs1;
        m0 = mn0; m1 = mn1;
        #pragma unroll
        for (int in = 0; in < 8; in++) {
            o[in][0] *= cr0; o[in][1] *= cr0;
            o[in][2] *= cr1; o[in][3] *= cr1;
        }

        // O += P @ V. P redistributed acc-layout -> A-fragment via shuffles:
        // P(row g, col c) of an 8-col block lives at lane 4g + c/2 (elem c&1).
        #pragma unroll
        for (int kk = 0; kk < 8; kk++) {
            int j0 = kk * 8;
            float e00 = __shfl_sync(0xFFFFFFFFu, sacc[kk][0], psrc0);
            float e01 = __shfl_sync(0xFFFFFFFFu, sacc[kk][1], psrc0);
            float e02 = __shfl_sync(0xFFFFFFFFu, sacc[kk][2], psrc0);
            float e03 = __shfl_sync(0xFFFFFFFFu, sacc[kk][3], psrc0);
            float e10 = __shfl_sync(0xFFFFFFFFu, sacc[kk][0], psrc1);
            float e11 = __shfl_sync(0xFFFFFFFFu, sacc[kk][1], psrc1);
            float e12 = __shfl_sync(0xFFFFFFFFu, sacc[kk][2], psrc1);
            float e13 = __shfl_sync(0xFFFFFFFFu, sacc[kk][3], psrc1);
            uint32_t a0 = f2tf(podd ? e01 : e00);
            uint32_t a1 = f2tf(podd ? e03 : e02);
            uint32_t a2 = f2tf(podd ? e11 : e10);
            uint32_t a3 = f2tf(podd ? e13 : e12);
            #pragma unroll
            for (int in = 0; in < 8; in++) {
                uint32_t b0 = Vc[(j0 + tig) * VP + in * 8 + gid];
                uint32_t b1 = Vc[(j0 + tig + 4) * VP + in * 8 + gid];
                mma_tf32(o[in], a0, a1, a2, a3, b0, b1);
            }
        }
    }

    // Epilogue: normalize, write Y as tf32 bits in [B, S, H*D]
    float inv0 = 1.0f / l0, inv1 = 1.0f / l1;
    #pragma unroll
    for (int in = 0; in < 8; in++) {
        int c = h * 64 + in * 8 + 2 * tig;
        uint2 v0 = make_uint2(f2tf(o[in][0] * inv0), f2tf(o[in][1] * inv0));
        uint2 v1 = make_uint2(f2tf(o[in][2] * inv1), f2tf(o[in][3] * inv1));
        *(uint2*)&g_Y[(size_t)(b * S + grow0) * E + c]     = v0;
        *(uint2*)&g_Y[(size_t)(b * S + grow0 + 8) * E + c] = v1;
    }
}

// ---------------------------------------------------------------------------
extern "C" void kernel_launch(void* const* d_in, const int* in_sizes, int n_in,
                              void* d_out, int out_size)
{
    (void)in_sizes; (void)n_in; (void)out_size;
    const float* x  = (const float*)d_in[0];
    const float* Wq = (const float*)d_in[1];
    const float* Wk = (const float*)d_in[2];
    const float* Wv = (const float*)d_in[3];
    const float* Wo = (const float*)d_in[4];
    const float* bo = (const float*)d_in[5];
    float* out = (float*)d_out;

    cudaFuncSetAttribute(qkv_kernel,
                         cudaFuncAttributeMaxDynamicSharedMemorySize, QKV_SMEM);
    cudaFuncSetAttribute(out_proj_kernel,
                         cudaFuncAttributeMaxDynamicSharedMemorySize, GEMM_SMEM);
    cudaFuncSetAttribute(attn_kernel,
                         cudaFuncAttributeMaxDynamicSharedMemorySize, ATTN_SMEM);

    sin_kernel<<<(S * 32 + 255) / 256, 256>>>();
    cvt_kernel<<<8 * 1024 * 1024 / (256 * 4), 256>>>(x, Wq, Wk, Wv, Wo);

    dim3 g1(E / 128, M_TOT / 128, 3);
    qkv_kernel<<<g1, 256, QKV_SMEM>>>();

    dim3 g2(S / 128, H, B);
    attn_kernel<<<g2, 256, ATTN_SMEM>>>();

    dim3 g3(E / 128, M_TOT / 128);
    out_proj_kernel<<<g3, 256, GEMM_SMEM>>>(bo, out);
}

// round 9
// speedup vs baseline: 3.7447x; 1.1295x over previous
#include <cuda_runtime.h>
#include <cuda_bf16.h>
#include <cuda_fp16.h>
#include <cstdint>
#include <math.h>

// Problem constants
constexpr int B = 2, S = 2048, H = 16, D = 64, E = 1024; // E = H*D
constexpr int M_TOT = B * S;                              // 4096

// Scratch (device globals — allocation-free).
__device__ uint32_t g_Q[(size_t)B * H * S * D];           // tf32 bits
__device__ uint32_t g_K[(size_t)B * H * S * D];           // tf32 bits
__device__ uint32_t g_Vh[(size_t)B * H * (S / 2) * D];    // half2 (key-pair, dim)
__device__ uint32_t g_Y[(size_t)M_TOT * E];               // tf32 bits
// tf32-converted inputs: [X: 0..4M) [Wq: 4M..5M) [Wk: 5M..6M) [Wv: 6M..7M) [Wo: 7M..8M)
constexpr size_t TF_X  = 0;
constexpr size_t TF_WQ = (size_t)4 * 1024 * 1024;
constexpr size_t TF_WK = (size_t)5 * 1024 * 1024;
constexpr size_t TF_WV = (size_t)6 * 1024 * 1024;
constexpr size_t TF_WO = (size_t)7 * 1024 * 1024;
__device__ uint32_t g_tf[(size_t)8 * 1024 * 1024];
__device__ float g_sin[(size_t)S * 32];

// ---------------------------------------------------------------------------
// mma helpers
// ---------------------------------------------------------------------------
__device__ __forceinline__ uint32_t f2tf(float f) {
    uint32_t u;
    asm("cvt.rna.tf32.f32 %0, %1;" : "=r"(u) : "f"(f));
    return u;
}

__device__ __forceinline__ void mma_tf32(float c[4],
                                         uint32_t a0, uint32_t a1, uint32_t a2, uint32_t a3,
                                         uint32_t b0, uint32_t b1) {
    asm volatile(
        "mma.sync.aligned.m16n8k8.row.col.f32.tf32.tf32.f32 "
        "{%0,%1,%2,%3},{%4,%5,%6,%7},{%8,%9},{%0,%1,%2,%3};"
        : "+f"(c[0]), "+f"(c[1]), "+f"(c[2]), "+f"(c[3])
        : "r"(a0), "r"(a1), "r"(a2), "r"(a3), "r"(b0), "r"(b1));
}

__device__ __forceinline__ void mma_f16(float c[4],
                                        uint32_t a0, uint32_t a1, uint32_t a2, uint32_t a3,
                                        uint32_t b0, uint32_t b1) {
    asm volatile(
        "mma.sync.aligned.m16n8k16.row.col.f32.f16.f16.f32 "
        "{%0,%1,%2,%3},{%4,%5,%6,%7},{%8,%9},{%0,%1,%2,%3};"
        : "+f"(c[0]), "+f"(c[1]), "+f"(c[2]), "+f"(c[3])
        : "r"(a0), "r"(a1), "r"(a2), "r"(a3), "r"(b0), "r"(b1));
}

__device__ __forceinline__ uint32_t pack_h2(float lo, float hi) {
    __half2 h = __floats2half2_rn(lo, hi);
    return *reinterpret_cast<uint32_t*>(&h);
}

__device__ __forceinline__ void cp16(uint32_t dst, const uint32_t* src) {
    asm volatile("cp.async.cg.shared.global [%0], [%1], 16;" :: "r"(dst), "l"(src));
}

// ---------------------------------------------------------------------------
// RoPE sin table (reference's c = sin bug replicated)
// ---------------------------------------------------------------------------
__global__ void sin_kernel() {
    int i = blockIdx.x * 256 + threadIdx.x;
    if (i < S * 32) {
        int s = i >> 5, j = i & 31;
        float theta = exp2f(-(float)j * (13.287712379549449f / 16.0f));
        g_sin[i] = sinf((float)s * theta);
    }
}

// ---------------------------------------------------------------------------
// Convert inputs to tf32 bits
// ---------------------------------------------------------------------------
__global__ __launch_bounds__(256) void cvt_kernel(
    const float* __restrict__ x,  const float* __restrict__ Wq,
    const float* __restrict__ Wk, const float* __restrict__ Wv,
    const float* __restrict__ Wo)
{
    size_t i = ((size_t)blockIdx.x * 256 + threadIdx.x) * 4;
    const float* src;
    size_t off;
    if (i < TF_WQ)      { src = x;  off = i; }
    else if (i < TF_WK) { src = Wq; off = i - TF_WQ; }
    else if (i < TF_WV) { src = Wk; off = i - TF_WK; }
    else if (i < TF_WO) { src = Wv; off = i - TF_WV; }
    else                { src = Wo; off = i - TF_WO; }
    float4 v = *(const float4*)&src[off];
    uint4 o = make_uint4(f2tf(v.x), f2tf(v.y), f2tf(v.z), f2tf(v.w));
    *(uint4*)&g_tf[i] = o;
}

// ---------------------------------------------------------------------------
// cp.async 4-stage tf32 GEMM mainloop (unchanged)
// ---------------------------------------------------------------------------
constexpr int NSTG = 4;
constexpr int AP_A = 20;
constexpr int AP_B = 136;
constexpr int ASTG_W = 128 * AP_A;
constexpr int BSTG_W = 16 * AP_B;
constexpr int STG_W  = ASTG_W + BSTG_W;
constexpr int GEMM_SMEM = NSTG * STG_W * 4;

__device__ __forceinline__ void gemm_issue(const uint32_t* Ag, const uint32_t* Bg,
                                           int row0, int col0, int k0,
                                           uint32_t abase, uint32_t bbase, int tid)
{
    int r0 = tid >> 2, kq = (tid & 3) * 4;
    cp16(abase + (uint32_t)(r0 * AP_A + kq) * 4,
         Ag + (size_t)(row0 + r0) * E + k0 + kq);
    cp16(abase + (uint32_t)((r0 + 64) * AP_A + kq) * 4,
         Ag + (size_t)(row0 + r0 + 64) * E + k0 + kq);
    int kr = tid >> 5, nq = (tid & 31) * 4;
    cp16(bbase + (uint32_t)(kr * AP_B + nq) * 4,
         Bg + (size_t)(k0 + kr) * E + col0 + nq);
    cp16(bbase + (uint32_t)((kr + 8) * AP_B + nq) * 4,
         Bg + (size_t)(k0 + kr + 8) * E + col0 + nq);
}

__device__ __forceinline__ void gemm_mma(const uint32_t* a, const uint32_t* b,
                                         float (&acc)[4][4][4],
                                         int wm, int wn, int gid, int tig)
{
    #pragma unroll
    for (int kk = 0; kk < 2; kk++) {
        int kc = kk * 8;
        uint32_t af[4][4], bf[4][2];
        #pragma unroll
        for (int im = 0; im < 4; im++) {
            int mb = wm * 64 + im * 16 + gid;
            af[im][0] = a[mb * AP_A + kc + tig];
            af[im][1] = a[(mb + 8) * AP_A + kc + tig];
            af[im][2] = a[mb * AP_A + kc + tig + 4];
            af[im][3] = a[(mb + 8) * AP_A + kc + tig + 4];
        }
        #pragma unroll
        for (int in = 0; in < 4; in++) {
            int nb = wn * 32 + in * 8 + gid;
            bf[in][0] = b[(kc + tig) * AP_B + nb];
            bf[in][1] = b[(kc + tig + 4) * AP_B + nb];
        }
        #pragma unroll
        for (int im = 0; im < 4; im++)
            #pragma unroll
            for (int in = 0; in < 4; in++)
                mma_tf32(acc[im][in], af[im][0], af[im][1], af[im][2], af[im][3],
                         bf[in][0], bf[in][1]);
    }
}

__device__ __forceinline__ void gemm128(const uint32_t* __restrict__ Ag,
                                        const uint32_t* __restrict__ Bg,
                                        int row0, int col0,
                                        uint32_t* sm, float (&acc)[4][4][4], int tid)
{
    const int lane = tid & 31, warp = tid >> 5;
    const int wm = warp >> 2, wn = warp & 3;
    const int gid = lane >> 2, tig = lane & 3;

    uint32_t smbase = (uint32_t)__cvta_generic_to_shared(sm);

    #pragma unroll
    for (int p = 0; p < 3; p++) {
        uint32_t ab = smbase + (uint32_t)(p * STG_W) * 4;
        gemm_issue(Ag, Bg, row0, col0, p * 16, ab, ab + ASTG_W * 4, tid);
        asm volatile("cp.async.commit_group;" ::: "memory");
    }

    const int NS = E / 16;
    for (int s = 0; s < NS; s++) {
        asm volatile("cp.async.wait_group 2;" ::: "memory");
        __syncthreads();
        if (s + 3 < NS) {
            int st = (s + 3) & 3;
            uint32_t ab = smbase + (uint32_t)(st * STG_W) * 4;
            gemm_issue(Ag, Bg, row0, col0, (s + 3) * 16, ab, ab + ASTG_W * 4, tid);
        }
        asm volatile("cp.async.commit_group;" ::: "memory");
        int cur = s & 3;
        gemm_mma(sm + cur * STG_W, sm + cur * STG_W + ASTG_W, acc, wm, wn, gid, tig);
    }
}

// ---------------------------------------------------------------------------
// QKV projection + fused RoPE epilogue.
// Q -> tf32 bits (pre-scaled 1/8), K -> tf32 bits, V -> half2 key-pair packed.
// ---------------------------------------------------------------------------
constexpr int QKV_SMEM = (GEMM_SMEM > 128 * 132 * 4) ? GEMM_SMEM : 128 * 132 * 4;

__global__ __launch_bounds__(256) void qkv_kernel()
{
    extern __shared__ uint32_t sm[];
    const int which = blockIdx.z;
    const uint32_t* W = g_tf + ((which == 0) ? TF_WQ : (which == 1) ? TF_WK : TF_WV);

    const int tid = threadIdx.x;
    const int row0 = blockIdx.y * 128;
    const int col0 = blockIdx.x * 128;

    float acc[4][4][4] = {};
    gemm128(g_tf + TF_X, W, row0, col0, sm, acc, tid);
    __syncthreads();

    float* Cs = (float*)sm; // [128][132]
    {
        const int lane = tid & 31, warp = tid >> 5;
        const int wm = warp >> 2, wn = warp & 3;
        const int gid = lane >> 2, tig = lane & 3;
        #pragma unroll
        for (int im = 0; im < 4; im++)
            #pragma unroll
            for (int in = 0; in < 4; in++) {
                int r = wm * 64 + im * 16 + gid;
                int c = wn * 32 + in * 8 + 2 * tig;
                Cs[r * 132 + c]           = acc[im][in][0];
                Cs[r * 132 + c + 1]       = acc[im][in][1];
                Cs[(r + 8) * 132 + c]     = acc[im][in][2];
                Cs[(r + 8) * 132 + c + 1] = acc[im][in][3];
            }
    }
    __syncthreads();

    const int h0 = col0 >> 6;
    if (which < 2) {
        // Q / K with RoPE
        uint32_t* out = (which == 0) ? g_Q : g_K;
        const float qs = (which == 0) ? 0.125f : 1.0f;
        #pragma unroll 4
        for (int it = 0; it < 64; it++) {
            int e = tid + it * 256;
            int r = e >> 7, c = e & 127;
            int grow = row0 + r;
            int b = grow >> 11, s = grow & 2047;
            int h = h0 + (c >> 6), d = c & 63;
            float sn = g_sin[(s << 5) + (d & 31)];
            float v0 = Cs[r * 132 + c];
            float vp = Cs[r * 132 + (c ^ 32)];
            float val = (d < 32) ? sn * (v0 - vp) : sn * (v0 + vp);
            out[(((b * H + h) * S) + s) * D + d] = f2tf(val * qs);
        }
    } else {
        // V: pack adjacent token rows into half2 -> g_Vh[b][h][s/2][d]
        #pragma unroll 4
        for (int it = 0; it < 32; it++) {
            int e = tid + it * 256;              // 64 row-pairs x 128 cols
            int rp = e >> 7, c = e & 127;
            int grow = row0 + 2 * rp;
            int b = grow >> 11, s = grow & 2047;
            int h = h0 + (c >> 6), d = c & 63;
            uint32_t pk = pack_h2(Cs[(2 * rp) * 132 + c], Cs[(2 * rp + 1) * 132 + c]);
            g_Vh[(((b * H + h) * (S / 2)) + (s >> 1)) * D + d] = pk;
        }
    }
}

// ---------------------------------------------------------------------------
// Output projection (unchanged)
// ---------------------------------------------------------------------------
__global__ __launch_bounds__(256) void out_proj_kernel(
    const float* __restrict__ bo, float* __restrict__ out)
{
    extern __shared__ uint32_t sm[];
    const int tid = threadIdx.x;
    const int row0 = blockIdx.y * 128;
    const int col0 = blockIdx.x * 128;

    float acc[4][4][4] = {};
    gemm128(g_Y, g_tf + TF_WO, row0, col0, sm, acc, tid);

    const int lane = tid & 31, warp = tid >> 5;
    const int wm = warp >> 2, wn = warp & 3;
    const int gid = lane >> 2, tig = lane & 3;

    #pragma unroll
    for (int im = 0; im < 4; im++)
        #pragma unroll
        for (int in = 0; in < 4; in++) {
            int r = row0 + wm * 64 + im * 16 + gid;
            int c = col0 + wn * 32 + in * 8 + 2 * tig;
            float b0 = bo[c], b1 = bo[c + 1];
            float2 v0 = make_float2(acc[im][in][0] + b0, acc[im][in][1] + b1);
            float2 v1 = make_float2(acc[im][in][2] + b0, acc[im][in][3] + b1);
            *(float2*)&out[(size_t)r * E + c]       = v0;
            *(float2*)&out[(size_t)(r + 8) * E + c] = v1;
        }
}

// ---------------------------------------------------------------------------
// Flash attention: QK in tf32 mma, PV in fp16 m16n8k16 with P passed directly
// from accumulators (FA2 layout identity) — no P smem, no shuffles.
// V in fp16 half2 (key-pair packed), cp.async double-buffered.
// ---------------------------------------------------------------------------
constexpr int AP = 68;               // pitch for Qs/Ks (uint32)
constexpr int VP = 72;               // pitch for Vh rows (uint32 = half2)
constexpr int KSTG = 64 * AP;        // K stage words
constexpr int VSTG = 32 * VP;        // V stage words (32 key-pair rows)
constexpr int ATTN_SMEM = (128 * AP + 2 * KSTG + 2 * VSTG) * 4; // 88064 B

__global__ __launch_bounds__(256, 2) void attn_kernel()
{
    extern __shared__ uint32_t sm[];
    uint32_t* Qs = sm;                     // [128][AP]
    uint32_t* Ks = Qs + 128 * AP;          // [2][64][AP]
    uint32_t* Vs = Ks + 2 * KSTG;          // [2][32][VP] half2

    const int qt = (gridDim.x - 1) - blockIdx.x; // heavy tiles first
    const int h = blockIdx.y, b = blockIdx.z;
    const int tid = threadIdx.x;
    const int w = tid >> 5, lane = tid & 31;
    const int gid = lane >> 2, tig = lane & 3;
    const int base = ((b * H + h) * S) * D;
    const int vbase = ((b * H + h) * (S / 2)) * D;
    const int q0 = qt * 128;

    const uint32_t ksb = (uint32_t)__cvta_generic_to_shared(Ks);
    const uint32_t vsb = (uint32_t)__cvta_generic_to_shared(Vs);

    auto issue_kv = [&](int k0, int buf) {
        #pragma unroll
        for (int i = 0; i < 4; i++) {
            int f = tid + i * 256;
            int j = f >> 4, dq = (f & 15) * 4;
            cp16(ksb + (uint32_t)(buf * KSTG + j * AP + dq) * 4,
                 g_K + base + (k0 + j) * D + dq);
        }
        // V: 32 key-pair rows x 64 half2 words = 512 quads -> 2 per thread
        #pragma unroll
        for (int i = 0; i < 2; i++) {
            int f = tid + i * 256;
            int jp = f >> 4, dq = (f & 15) * 4;
            cp16(vsb + (uint32_t)(buf * VSTG + jp * VP + dq) * 4,
                 g_Vh + vbase + ((k0 >> 1) + jp) * D + dq);
        }
        asm volatile("cp.async.commit_group;" ::: "memory");
    };

    issue_kv(0, 0);
    #pragma unroll
    for (int it = 0; it < 8; it++) {
        int f = tid + it * 256;
        int row = f >> 4, dq = (f & 15) * 4;
        uint4 v = *(const uint4*)&g_Q[base + (q0 + row) * D + dq];
        *(uint4*)&Qs[row * AP + dq] = v;
    }

    const int r0 = w * 16 + gid;
    const int grow0 = q0 + r0;

    float m0 = -1e30f, m1 = -1e30f, l0 = 0.0f, l1 = 0.0f;
    float o[8][4] = {};

    const int NKT = 2 * qt + 2;
    for (int kt = 0; kt < NKT; kt++) {
        const int cur = kt & 1, nxt = cur ^ 1;
        __syncthreads(); // all warps done reading buffer `nxt` from iter kt-1
        if (kt + 1 < NKT) issue_kv((kt + 1) * 64, nxt);
        else asm volatile("cp.async.commit_group;" ::: "memory");
        asm volatile("cp.async.wait_group 1;" ::: "memory");
        __syncthreads();

        const uint32_t* Kc = Ks + cur * KSTG;
        const uint32_t* Vc = Vs + cur * VSTG;
        const int k0 = kt * 64;

        // S = Q @ K^T (tf32)
        float sacc[8][4] = {};
        #pragma unroll
        for (int kk = 0; kk < 8; kk++) {
            int d0 = kk * 8;
            uint32_t a0 = Qs[r0 * AP + d0 + tig];
            uint32_t a1 = Qs[(r0 + 8) * AP + d0 + tig];
            uint32_t a2 = Qs[r0 * AP + d0 + tig + 4];
            uint32_t a3 = Qs[(r0 + 8) * AP + d0 + tig + 4];
            #pragma unroll
            for (int in = 0; in < 8; in++) {
                uint32_t b0 = Kc[(in * 8 + gid) * AP + d0 + tig];
                uint32_t b1 = Kc[(in * 8 + gid) * AP + d0 + tig + 4];
                mma_tf32(sacc[in], a0, a1, a2, a3, b0, b1);
            }
        }

        // Causal mask (only the last two k-tiles cross the diagonal)
        if (kt >= 2 * qt) {
            #pragma unroll
            for (int in = 0; in < 8; in++) {
                int gc = k0 + in * 8 + 2 * tig;
                if (gc     > grow0)     sacc[in][0] = -1e30f;
                if (gc + 1 > grow0)     sacc[in][1] = -1e30f;
                if (gc     > grow0 + 8) sacc[in][2] = -1e30f;
                if (gc + 1 > grow0 + 8) sacc[in][3] = -1e30f;
            }
        }

        // Online softmax (rows r0, r0+8; reduce over the 4 tig lanes)
        float mx0 = -1e30f, mx1 = -1e30f;
        #pragma unroll
        for (int in = 0; in < 8; in++) {
            mx0 = fmaxf(mx0, fmaxf(sacc[in][0], sacc[in][1]));
            mx1 = fmaxf(mx1, fmaxf(sacc[in][2], sacc[in][3]));
        }
        mx0 = fmaxf(mx0, __shfl_xor_sync(0xFFFFFFFFu, mx0, 1));
        mx0 = fmaxf(mx0, __shfl_xor_sync(0xFFFFFFFFu, mx0, 2));
        mx1 = fmaxf(mx1, __shfl_xor_sync(0xFFFFFFFFu, mx1, 1));
        mx1 = fmaxf(mx1, __shfl_xor_sync(0xFFFFFFFFu, mx1, 2));
        float mn0 = fmaxf(m0, mx0), mn1 = fmaxf(m1, mx1);
        float cr0 = __expf(m0 - mn0), cr1 = __expf(m1 - mn1);

        float rs0 = 0.0f, rs1 = 0.0f;
        #pragma unroll
        for (int in = 0; in < 8; in++) {
            sacc[in][0] = __expf(sacc[in][0] - mn0);
            sacc[in][1] = __expf(sacc[in][1] - mn0);
            sacc[in][2] = __expf(sacc[in][2] - mn1);
            sacc[in][3] = __expf(sacc[in][3] - mn1);
            rs0 += sacc[in][0] + sacc[in][1];
            rs1 += sacc[in][2] + sacc[in][3];
        }
        rs0 += __shfl_xor_sync(0xFFFFFFFFu, rs0, 1);
        rs0 += __shfl_xor_sync(0xFFFFFFFFu, rs0, 2);
        rs1 += __shfl_xor_sync(0xFFFFFFFFu, rs1, 1);
        rs1 += __shfl_xor_sync(0xFFFFFFFFu, rs1, 2);
        l0 = l0 * cr0 + rs0;
        l1 = l1 * cr1 + rs1;
        m0 = mn0; m1 = mn1;
        #pragma unroll
        for (int in = 0; in < 8; in++) {
            o[in][0] *= cr0; o[in][1] *= cr0;
            o[in][2] *= cr1; o[in][3] *= cr1;
        }

        // O += P @ V  (fp16 m16n8k16; P acc layout == A fragment layout)
        #pragma unroll
        for (int kk = 0; kk < 4; kk++) {
            uint32_t a0 = pack_h2(sacc[2 * kk][0],     sacc[2 * kk][1]);
            uint32_t a1 = pack_h2(sacc[2 * kk][2],     sacc[2 * kk][3]);
            uint32_t a2 = pack_h2(sacc[2 * kk + 1][0], sacc[2 * kk + 1][1]);
            uint32_t a3 = pack_h2(sacc[2 * kk + 1][2], sacc[2 * kk + 1][3]);
            int jp0 = kk * 8;
            #pragma unroll
            for (int in = 0; in < 8; in++) {
                uint32_t b0 = Vc[(jp0 + tig) * VP + in * 8 + gid];
                uint32_t b1 = Vc[(jp0 + tig + 4) * VP + in * 8 + gid];
                mma_f16(o[in], a0, a1, a2, a3, b0, b1);
            }
        }
    }

    // Epilogue: normalize, write Y as tf32 bits in [B, S, H*D]
    float inv0 = 1.0f / l0, inv1 = 1.0f / l1;
    #pragma unroll
    for (int in = 0; in < 8; in++) {
        int c = h * 64 + in * 8 + 2 * tig;
        uint2 v0 = make_uint2(f2tf(o[in][0] * inv0), f2tf(o[in][1] * inv0));
        uint2 v1 = make_uint2(f2tf(o[in][2] * inv1), f2tf(o[in][3] * inv1));
        *(uint2*)&g_Y[(size_t)(b * S + grow0) * E + c]     = v0;
        *(uint2*)&g_Y[(size_t)(b * S + grow0 + 8) * E + c] = v1;
    }
}

// ---------------------------------------------------------------------------
extern "C" void kernel_launch(void* const* d_in, const int* in_sizes, int n_in,
                              void* d_out, int out_size)
{
    (void)in_sizes; (void)n_in; (void)out_size;
    const float* x  = (const float*)d_in[0];
    const float* Wq = (const float*)d_in[1];
    const float* Wk = (const float*)d_in[2];
    const float* Wv = (const float*)d_in[3];
    const float* Wo = (const float*)d_in[4];
    const float* bo = (const float*)d_in[5];
    float* out = (float*)d_out;

    cudaFuncSetAttribute(qkv_kernel,
                         cudaFuncAttributeMaxDynamicSharedMemorySize, QKV_SMEM);
    cudaFuncSetAttribute(out_proj_kernel,
                         cudaFuncAttributeMaxDynamicSharedMemorySize, GEMM_SMEM);
    cudaFuncSetAttribute(attn_kernel,
                         cudaFuncAttributeMaxDynamicSharedMemorySize, ATTN_SMEM);

    sin_kernel<<<(S * 32 + 255) / 256, 256>>>();
    cvt_kernel<<<8 * 1024 * 1024 / (256 * 4), 256>>>(x, Wq, Wk, Wv, Wo);

    dim3 g1(E / 128, M_TOT / 128, 3);
    qkv_kernel<<<g1, 256, QKV_SMEM>>>();

    dim3 g2(S / 128, H, B);
    attn_kernel<<<g2, 256, ATTN_SMEM>>>();

    dim3 g3(E / 128, M_TOT / 128);
    out_proj_kernel<<<g3, 256, GEMM_SMEM>>>(bo, out);
}

// round 10
// speedup vs baseline: 5.8530x; 1.5630x over previous
#include <cuda_runtime.h>
#include <cuda_bf16.h>
#include <cuda_fp16.h>
#include <cstdint>
#include <math.h>

// Problem constants
constexpr int B = 2, S = 2048, H = 16, D = 64, E = 1024; // E = H*D
constexpr int M_TOT = B * S;                              // 4096
constexpr int EW = E / 2;                                 // 512 half2 words per row
constexpr int DW = D / 2;                                 // 32 half2 words per head row
constexpr size_t WH_MAT = (size_t)E * EW;                 // words per transposed W

// Scratch (device globals — allocation-free). uint32 = half2 packed.
__device__ uint32_t g_Xh[(size_t)M_TOT * EW];             // X fp16 [m][kw]
__device__ uint32_t g_Wh[(size_t)4 * WH_MAT];             // Wq,Wk,Wv,Wo transposed fp16 [n][kw]
__device__ uint32_t g_Qh[(size_t)B * H * S * DW];         // Q fp16 [token][dw] (pre-scaled 1/8)
__device__ uint32_t g_Kh[(size_t)B * H * S * DW];         // K fp16 [token][dw]
__device__ uint32_t g_Vh[(size_t)B * H * (S / 2) * D];    // V fp16 half2 (key-pair, dim)
__device__ uint32_t g_Yh[(size_t)M_TOT * EW];             // Y fp16 [m][kw]
__device__ float g_sin[(size_t)S * 32];

// ---------------------------------------------------------------------------
// helpers
// ---------------------------------------------------------------------------
__device__ __forceinline__ void mma_f16(float c[4],
                                        uint32_t a0, uint32_t a1, uint32_t a2, uint32_t a3,
                                        uint32_t b0, uint32_t b1) {
    asm volatile(
        "mma.sync.aligned.m16n8k16.row.col.f32.f16.f16.f32 "
        "{%0,%1,%2,%3},{%4,%5,%6,%7},{%8,%9},{%0,%1,%2,%3};"
        : "+f"(c[0]), "+f"(c[1]), "+f"(c[2]), "+f"(c[3])
        : "r"(a0), "r"(a1), "r"(a2), "r"(a3), "r"(b0), "r"(b1));
}

__device__ __forceinline__ uint32_t pack_h2(float lo, float hi) {
    __half2 h = __floats2half2_rn(lo, hi);
    return *reinterpret_cast<uint32_t*>(&h);
}

__device__ __forceinline__ void cp16(uint32_t dst, const uint32_t* src) {
    asm volatile("cp.async.cg.shared.global [%0], [%1], 16;" :: "r"(dst), "l"(src));
}

// ---------------------------------------------------------------------------
// RoPE sin table (reference's c = sin bug replicated)
// ---------------------------------------------------------------------------
__global__ void sin_kernel() {
    int i = blockIdx.x * 256 + threadIdx.x;
    if (i < S * 32) {
        int s = i >> 5, j = i & 31;
        float theta = exp2f(-(float)j * (13.287712379549449f / 16.0f));
        g_sin[i] = sinf((float)s * theta);
    }
}

// ---------------------------------------------------------------------------
// X -> fp16 packed [m][kw]
// ---------------------------------------------------------------------------
__global__ __launch_bounds__(256) void cvt_x_kernel(const float* __restrict__ x)
{
    size_t i8 = ((size_t)blockIdx.x * 256 + threadIdx.x) * 8;
    float4 v0 = *(const float4*)&x[i8];
    float4 v1 = *(const float4*)&x[i8 + 4];
    uint4 o = make_uint4(pack_h2(v0.x, v0.y), pack_h2(v0.z, v0.w),
                         pack_h2(v1.x, v1.y), pack_h2(v1.z, v1.w));
    *(uint4*)&g_Xh[i8 / 2] = o;
}

// ---------------------------------------------------------------------------
// W -> transposed fp16 [n][kw] via smem tile (64x64)
// ---------------------------------------------------------------------------
__global__ __launch_bounds__(256) void transpose_w_kernel(
    const float* __restrict__ Wq, const float* __restrict__ Wk,
    const float* __restrict__ Wv, const float* __restrict__ Wo)
{
    __shared__ float ts[64][68];
    const int mat = blockIdx.z;
    const float* W = (mat == 0) ? Wq : (mat == 1) ? Wk : (mat == 2) ? Wv : Wo;
    const int k0 = blockIdx.x * 64, n0 = blockIdx.y * 64;
    const int tid = threadIdx.x;

    #pragma unroll
    for (int i = 0; i < 4; i++) {
        int f = tid + i * 256;
        int r = f >> 4, cq = (f & 15) * 4;
        float4 v = *(const float4*)&W[(size_t)(k0 + r) * E + n0 + cq];
        ts[r][cq] = v.x; ts[r][cq + 1] = v.y; ts[r][cq + 2] = v.z; ts[r][cq + 3] = v.w;
    }
    __syncthreads();

    // each thread: output row n0 + c, 8 consecutive kw words
    int c = tid >> 2, wq = (tid & 3) * 8;
    uint32_t* dst = g_Wh + mat * WH_MAT + (size_t)(n0 + c) * EW + k0 / 2 + wq;
    #pragma unroll
    for (int w = 0; w < 8; w++)
        dst[w] = pack_h2(ts[2 * (wq + w)][c], ts[2 * (wq + w) + 1][c]);
}

// ---------------------------------------------------------------------------
// fp16 cp.async 4-stage GEMM mainloop. C[128,128] = A[4096,1024] @ W[1024,1024]
// A: [m][kw] fp16, Bt: [n][kw] fp16 (transposed W). k-slab = 32 dims = 16 words.
// smem stage: A[128][20] + B[128][20] words. 8 warps (2m x 4n), m16n8k16.
// ---------------------------------------------------------------------------
constexpr int GP = 20;                    // smem pitch (words)
constexpr int HSTG_W = 2 * 128 * GP;      // words per stage (A+B) = 5120
constexpr int GEMM_SMEM = 4 * HSTG_W * 4; // 81920 B

__device__ __forceinline__ void gemm_issue(const uint32_t* Ah, const uint32_t* Bt,
                                           int row0, int col0, int kw0,
                                           uint32_t abase, int tid)
{
    uint32_t bbase = abase + 128 * GP * 4;
    #pragma unroll
    for (int i = 0; i < 2; i++) {
        int f = tid + i * 256;
        int r = f >> 2, qw = (f & 3) * 4;
        cp16(abase + (uint32_t)(r * GP + qw) * 4,
             Ah + (size_t)(row0 + r) * EW + kw0 + qw);
        cp16(bbase + (uint32_t)(r * GP + qw) * 4,
             Bt + (size_t)(col0 + r) * EW + kw0 + qw);
    }
}

__device__ __forceinline__ void gemm_mma(const uint32_t* a, const uint32_t* b,
                                         float (&acc)[4][4][4],
                                         int wm, int wn, int gid, int tig)
{
    #pragma unroll
    for (int s = 0; s < 2; s++) {
        int w0 = 8 * s + tig, w1 = w0 + 4;
        uint32_t af[4][4], bf[4][2];
        #pragma unroll
        for (int im = 0; im < 4; im++) {
            int mb = wm * 64 + im * 16 + gid;
            af[im][0] = a[mb * GP + w0];
            af[im][1] = a[(mb + 8) * GP + w0];
            af[im][2] = a[mb * GP + w1];
            af[im][3] = a[(mb + 8) * GP + w1];
        }
        #pragma unroll
        for (int in = 0; in < 4; in++) {
            int nb = wn * 32 + in * 8 + gid;
            bf[in][0] = b[nb * GP + w0];
            bf[in][1] = b[nb * GP + w1];
        }
        #pragma unroll
        for (int im = 0; im < 4; im++)
            #pragma unroll
            for (int in = 0; in < 4; in++)
                mma_f16(acc[im][in], af[im][0], af[im][1], af[im][2], af[im][3],
                        bf[in][0], bf[in][1]);
    }
}

__device__ __forceinline__ void gemm128(const uint32_t* __restrict__ Ah,
                                        const uint32_t* __restrict__ Bt,
                                        int row0, int col0,
                                        uint32_t* sm, float (&acc)[4][4][4], int tid)
{
    const int lane = tid & 31, warp = tid >> 5;
    const int wm = warp >> 2, wn = warp & 3;
    const int gid = lane >> 2, tig = lane & 3;

    uint32_t smbase = (uint32_t)__cvta_generic_to_shared(sm);

    #pragma unroll
    for (int p = 0; p < 3; p++) {
        gemm_issue(Ah, Bt, row0, col0, p * 16, smbase + (uint32_t)(p * HSTG_W) * 4, tid);
        asm volatile("cp.async.commit_group;" ::: "memory");
    }

    const int NS = EW / 16; // 32 stages of 16 words (32 dims)
    for (int s = 0; s < NS; s++) {
        asm volatile("cp.async.wait_group 2;" ::: "memory");
        __syncthreads();
        if (s + 3 < NS) {
            int st = (s + 3) & 3;
            gemm_issue(Ah, Bt, row0, col0, (s + 3) * 16,
                       smbase + (uint32_t)(st * HSTG_W) * 4, tid);
        }
        asm volatile("cp.async.commit_group;" ::: "memory");
        int cur = s & 3;
        gemm_mma(sm + cur * HSTG_W, sm + cur * HSTG_W + 128 * GP, acc, wm, wn, gid, tig);
    }
}

// ---------------------------------------------------------------------------
// QKV projection + fused RoPE epilogue.
// Q -> fp16 [token][dw] pre-scaled 1/8; K -> fp16 [token][dw];
// V -> fp16 half2 key-pair packed [token-pair][d].
// ---------------------------------------------------------------------------
constexpr int QKV_SMEM = GEMM_SMEM; // 81920 >= 128*132*4 = 67584

__global__ __launch_bounds__(256) void qkv_kernel()
{
    extern __shared__ uint32_t sm[];
    const int which = blockIdx.z;

    const int tid = threadIdx.x;
    const int row0 = blockIdx.y * 128;
    const int col0 = blockIdx.x * 128;

    float acc[4][4][4] = {};
    gemm128(g_Xh, g_Wh + which * WH_MAT, row0, col0, sm, acc, tid);
    __syncthreads();

    float* Cs = (float*)sm; // [128][132]
    {
        const int lane = tid & 31, warp = tid >> 5;
        const int wm = warp >> 2, wn = warp & 3;
        const int gid = lane >> 2, tig = lane & 3;
        #pragma unroll
        for (int im = 0; im < 4; im++)
            #pragma unroll
            for (int in = 0; in < 4; in++) {
                int r = wm * 64 + im * 16 + gid;
                int c = wn * 32 + in * 8 + 2 * tig;
                Cs[r * 132 + c]           = acc[im][in][0];
                Cs[r * 132 + c + 1]       = acc[im][in][1];
                Cs[(r + 8) * 132 + c]     = acc[im][in][2];
                Cs[(r + 8) * 132 + c + 1] = acc[im][in][3];
            }
    }
    __syncthreads();

    const int h0 = col0 >> 6;
    if (which < 2) {
        // Q / K with RoPE, packed fp16 pairs of adjacent dims
        uint32_t* out = (which == 0) ? g_Qh : g_Kh;
        const float qs = (which == 0) ? 0.125f : 1.0f;
        #pragma unroll 4
        for (int it = 0; it < 32; it++) {
            int e = tid + it * 256;             // 128 rows x 64 word-cols
            int r = e >> 6, cw = e & 63;
            int c = 2 * cw;
            int grow = row0 + r;
            int b = grow >> 11, s = grow & 2047;
            int h = h0 + (c >> 6), d = c & 63;
            float sn0 = g_sin[(s << 5) + (d & 31)];
            float sn1 = g_sin[(s << 5) + ((d + 1) & 31)];
            float v0 = Cs[r * 132 + c],       p0 = Cs[r * 132 + (c ^ 32)];
            float v1 = Cs[r * 132 + c + 1],   p1 = Cs[r * 132 + ((c + 1) ^ 32)];
            float val0 = (d < 32) ? sn0 * (v0 - p0) : sn0 * (v0 + p0);
            float val1 = (d < 32) ? sn1 * (v1 - p1) : sn1 * (v1 + p1);
            out[(size_t)(((b * H + h) * S) + s) * DW + (d >> 1)] =
                pack_h2(val0 * qs, val1 * qs);
        }
    } else {
        // V: pack adjacent token rows into half2 -> g_Vh[b][h][s/2][d]
        #pragma unroll 4
        for (int it = 0; it < 32; it++) {
            int e = tid + it * 256;             // 64 row-pairs x 128 cols
            int rp = e >> 7, c = e & 127;
            int grow = row0 + 2 * rp;
            int b = grow >> 11, s = grow & 2047;
            int h = h0 + (c >> 6), d = c & 63;
            uint32_t pk = pack_h2(Cs[(2 * rp) * 132 + c], Cs[(2 * rp + 1) * 132 + c]);
            g_Vh[(((b * H + h) * (S / 2)) + (s >> 1)) * D + d] = pk;
        }
    }
}

// ---------------------------------------------------------------------------
// Output projection: out = Y @ Wo + bo (fp32 out)
// ---------------------------------------------------------------------------
__global__ __launch_bounds__(256) void out_proj_kernel(
    const float* __restrict__ bo, float* __restrict__ out)
{
    extern __shared__ uint32_t sm[];
    const int tid = threadIdx.x;
    const int row0 = blockIdx.y * 128;
    const int col0 = blockIdx.x * 128;

    float acc[4][4][4] = {};
    gemm128(g_Yh, g_Wh + 3 * WH_MAT, row0, col0, sm, acc, tid);

    const int lane = tid & 31, warp = tid >> 5;
    const int wm = warp >> 2, wn = warp & 3;
    const int gid = lane >> 2, tig = lane & 3;

    #pragma unroll
    for (int im = 0; im < 4; im++)
        #pragma unroll
        for (int in = 0; in < 4; in++) {
            int r = row0 + wm * 64 + im * 16 + gid;
            int c = col0 + wn * 32 + in * 8 + 2 * tig;
            float b0 = bo[c], b1 = bo[c + 1];
            float2 v0 = make_float2(acc[im][in][0] + b0, acc[im][in][1] + b1);
            float2 v1 = make_float2(acc[im][in][2] + b0, acc[im][in][3] + b1);
            *(float2*)&out[(size_t)r * E + c]       = v0;
            *(float2*)&out[(size_t)(r + 8) * E + c] = v1;
        }
}

// ---------------------------------------------------------------------------
// Flash attention, full fp16 mma (fp32 accum & softmax), cp.async dbl-buffered.
// Qs [128][36], Ks [2][64][36] ([n][kw] layout), Vs [2][32][72] (key-pair rows).
// ---------------------------------------------------------------------------
constexpr int QKP = 36;              // pitch for Qs/Ks (words)
constexpr int VP = 72;               // pitch for Vs (words)
constexpr int KSTG = 64 * QKP;       // 2304 words
constexpr int VSTG = 32 * VP;        // 2304 words
constexpr int ATTN_SMEM = (128 * QKP + 2 * KSTG + 2 * VSTG) * 4; // 55296 B

__global__ __launch_bounds__(256, 2) void attn_kernel()
{
    extern __shared__ uint32_t sm[];
    uint32_t* Qs = sm;                     // [128][QKP]
    uint32_t* Ks = Qs + 128 * QKP;         // [2][64][QKP]
    uint32_t* Vs = Ks + 2 * KSTG;          // [2][32][VP]

    const int qt = (gridDim.x - 1) - blockIdx.x; // heavy tiles first
    const int h = blockIdx.y, b = blockIdx.z;
    const int tid = threadIdx.x;
    const int w = tid >> 5, lane = tid & 31;
    const int gid = lane >> 2, tig = lane & 3;
    const int qkbase = ((b * H + h) * S) * DW;
    const int vbase = ((b * H + h) * (S / 2)) * D;
    const int q0 = qt * 128;

    const uint32_t ksb = (uint32_t)__cvta_generic_to_shared(Ks);
    const uint32_t vsb = (uint32_t)__cvta_generic_to_shared(Vs);

    auto issue_kv = [&](int k0, int buf) {
        // K: 64 rows x 32 words = 512 quads -> 2/thread
        #pragma unroll
        for (int i = 0; i < 2; i++) {
            int f = tid + i * 256;
            int j = f >> 3, qw = (f & 7) * 4;
            cp16(ksb + (uint32_t)(buf * KSTG + j * QKP + qw) * 4,
                 g_Kh + qkbase + (k0 + j) * DW + qw);
        }
        // V: 32 key-pair rows x 64 words = 512 quads -> 2/thread
        #pragma unroll
        for (int i = 0; i < 2; i++) {
            int f = tid + i * 256;
            int jp = f >> 4, dq = (f & 15) * 4;
            cp16(vsb + (uint32_t)(buf * VSTG + jp * VP + dq) * 4,
                 g_Vh + vbase + ((k0 >> 1) + jp) * D + dq);
        }
        asm volatile("cp.async.commit_group;" ::: "memory");
    };

    issue_kv(0, 0);
    // Q: 128 rows x 32 words = 1024 quads -> 4/thread
    #pragma unroll
    for (int it = 0; it < 4; it++) {
        int f = tid + it * 256;
        int row = f >> 3, qw = (f & 7) * 4;
        uint4 v = *(const uint4*)&g_Qh[qkbase + (q0 + row) * DW + qw];
        *(uint4*)&Qs[row * QKP + qw] = v;
    }

    const int r0 = w * 16 + gid;
    const int grow0 = q0 + r0;

    float m0 = -1e30f, m1 = -1e30f, l0 = 0.0f, l1 = 0.0f;
    float o[8][4] = {};

    const int NKT = 2 * qt + 2;
    for (int kt = 0; kt < NKT; kt++) {
        const int cur = kt & 1, nxt = cur ^ 1;
        __syncthreads(); // all warps done reading buffer `nxt` from iter kt-1
        if (kt + 1 < NKT) issue_kv((kt + 1) * 64, nxt);
        else asm volatile("cp.async.commit_group;" ::: "memory");
        asm volatile("cp.async.wait_group 1;" ::: "memory");
        __syncthreads();

        const uint32_t* Kc = Ks + cur * KSTG;
        const uint32_t* Vc = Vs + cur * VSTG;
        const int k0 = kt * 64;

        // S = Q @ K^T (fp16 inputs, fp32 accum)
        float sacc[8][4] = {};
        #pragma unroll
        for (int kk = 0; kk < 4; kk++) {
            int w0 = 8 * kk + tig, w1 = w0 + 4;
            uint32_t a0 = Qs[r0 * QKP + w0];
            uint32_t a1 = Qs[(r0 + 8) * QKP + w0];
            uint32_t a2 = Qs[r0 * QKP + w1];
            uint32_t a3 = Qs[(r0 + 8) * QKP + w1];
            #pragma unroll
            for (int in = 0; in < 8; in++) {
                uint32_t b0 = Kc[(in * 8 + gid) * QKP + w0];
                uint32_t b1 = Kc[(in * 8 + gid) * QKP + w1];
                mma_f16(sacc[in], a0, a1, a2, a3, b0, b1);
            }
        }

        // Causal mask (only the last two k-tiles cross the diagonal)
        if (kt >= 2 * qt) {
            #pragma unroll
            for (int in = 0; in < 8; in++) {
                int gc = k0 + in * 8 + 2 * tig;
                if (gc     > grow0)     sacc[in][0] = -1e30f;
                if (gc + 1 > grow0)     sacc[in][1] = -1e30f;
                if (gc     > grow0 + 8) sacc[in][2] = -1e30f;
                if (gc + 1 > grow0 + 8) sacc[in][3] = -1e30f;
            }
        }

        // Online softmax (rows r0, r0+8; reduce over the 4 tig lanes)
        float mx0 = -1e30f, mx1 = -1e30f;
        #pragma unroll
        for (int in = 0; in < 8; in++) {
            mx0 = fmaxf(mx0, fmaxf(sacc[in][0], sacc[in][1]));
            mx1 = fmaxf(mx1, fmaxf(sacc[in][2], sacc[in][3]));
        }
        mx0 = fmaxf(mx0, __shfl_xor_sync(0xFFFFFFFFu, mx0, 1));
        mx0 = fmaxf(mx0, __shfl_xor_sync(0xFFFFFFFFu, mx0, 2));
        mx1 = fmaxf(mx1, __shfl_xor_sync(0xFFFFFFFFu, mx1, 1));
        mx1 = fmaxf(mx1, __shfl_xor_sync(0xFFFFFFFFu, mx1, 2));
        float mn0 = fmaxf(m0, mx0), mn1 = fmaxf(m1, mx1);
        float cr0 = __expf(m0 - mn0), cr1 = __expf(m1 - mn1);

        float rs0 = 0.0f, rs1 = 0.0f;
        #pragma unroll
        for (int in = 0; in < 8; in++) {
            sacc[in][0] = __expf(sacc[in][0] - mn0);
            sacc[in][1] = __expf(sacc[in][1] - mn0);
            sacc[in][2] = __expf(sacc[in][2] - mn1);
            sacc[in][3] = __expf(sacc[in][3] - mn1);
            rs0 += sacc[in][0] + sacc[in][1];
            rs1 += sacc[in][2] + sacc[in][3];
        }
        rs0 += __shfl_xor_sync(0xFFFFFFFFu, rs0, 1);
        rs0 += __shfl_xor_sync(0xFFFFFFFFu, rs0, 2);
        rs1 += __shfl_xor_sync(0xFFFFFFFFu, rs1, 1);
        rs1 += __shfl_xor_sync(0xFFFFFFFFu, rs1, 2);
        l0 = l0 * cr0 + rs0;
        l1 = l1 * cr1 + rs1;
        m0 = mn0; m1 = mn1;
        #pragma unroll
        for (int in = 0; in < 8; in++) {
            o[in][0] *= cr0; o[in][1] *= cr0;
            o[in][2] *= cr1; o[in][3] *= cr1;
        }

        // O += P @ V  (fp16; P acc layout == A fragment layout)
        #pragma unroll
        for (int kk = 0; kk < 4; kk++) {
            uint32_t a0 = pack_h2(sacc[2 * kk][0],     sacc[2 * kk][1]);
            uint32_t a1 = pack_h2(sacc[2 * kk][2],     sacc[2 * kk][3]);
            uint32_t a2 = pack_h2(sacc[2 * kk + 1][0], sacc[2 * kk + 1][1]);
            uint32_t a3 = pack_h2(sacc[2 * kk + 1][2], sacc[2 * kk + 1][3]);
            int jp0 = kk * 8;
            #pragma unroll
            for (int in = 0; in < 8; in++) {
                uint32_t b0 = Vc[(jp0 + tig) * VP + in * 8 + gid];
                uint32_t b1 = Vc[(jp0 + tig + 4) * VP + in * 8 + gid];
                mma_f16(o[in], a0, a1, a2, a3, b0, b1);
            }
        }
    }

    // Epilogue: normalize, write Y as fp16 words [m][kw]
    float inv0 = 1.0f / l0, inv1 = 1.0f / l1;
    #pragma unroll
    for (int in = 0; in < 8; in++) {
        int cw = h * 32 + in * 4 + tig;  // word column
        g_Yh[(size_t)(b * S + grow0) * EW + cw]     = pack_h2(o[in][0] * inv0, o[in][1] * inv0);
        g_Yh[(size_t)(b * S + grow0 + 8) * EW + cw] = pack_h2(o[in][2] * inv1, o[in][3] * inv1);
    }
}

// ---------------------------------------------------------------------------
extern "C" void kernel_launch(void* const* d_in, const int* in_sizes, int n_in,
                              void* d_out, int out_size)
{
    (void)in_sizes; (void)n_in; (void)out_size;
    const float* x  = (const float*)d_in[0];
    const float* Wq = (const float*)d_in[1];
    const float* Wk = (const float*)d_in[2];
    const float* Wv = (const float*)d_in[3];
    const float* Wo = (const float*)d_in[4];
    const float* bo = (const float*)d_in[5];
    float* out = (float*)d_out;

    cudaFuncSetAttribute(qkv_kernel,
                         cudaFuncAttributeMaxDynamicSharedMemorySize, QKV_SMEM);
    cudaFuncSetAttribute(out_proj_kernel,
                         cudaFuncAttributeMaxDynamicSharedMemorySize, GEMM_SMEM);
    cudaFuncSetAttribute(attn_kernel,
                         cudaFuncAttributeMaxDynamicSharedMemorySize, ATTN_SMEM);

    sin_kernel<<<(S * 32 + 255) / 256, 256>>>();
    cvt_x_kernel<<<(M_TOT * E) / (256 * 8), 256>>>(x);
    dim3 gt(E / 64, E / 64, 4);
    transpose_w_kernel<<<gt, 256>>>(Wq, Wk, Wv, Wo);

    dim3 g1(E / 128, M_TOT / 128, 3);
    qkv_kernel<<<g1, 256, QKV_SMEM>>>();

    dim3 g2(S / 128, H, B);
    attn_kernel<<<g2, 256, ATTN_SMEM>>>();

    dim3 g3(E / 128, M_TOT / 128);
    out_proj_kernel<<<g3, 256, GEMM_SMEM>>>(bo, out);
}